// round 8
// baseline (speedup 1.0000x reference)
#include <cuda_runtime.h>
#include <cuda_bf16.h>
#include <cstdint>

#define BB 4
#define SS 2048
#define HH 2048
#define NHH 16
#define HDD 128
#define MROWS (BB*SS)      /* 8192 */
#define QKVN (3*HH)        /* 6144 */

// ---------------- scratch (static device allocations are allowed) ----------
__device__ __nv_bfloat16 g_xn_hi[(size_t)MROWS * HH];
__device__ __nv_bfloat16 g_xn_lo[(size_t)MROWS * HH];
__device__ float         g_qkv [(size_t)MROWS * QKVN];
__device__ __nv_bfloat16 g_o_hi [(size_t)MROWS * HH];
__device__ __nv_bfloat16 g_o_lo [(size_t)MROWS * HH];
__device__ __nv_bfloat16 g_wa_hi[(size_t)QKVN * HH];   // c_attn_w^T hi : [6144][2048]
__device__ __nv_bfloat16 g_wa_lo[(size_t)QKVN * HH];
__device__ __nv_bfloat16 g_wp_hi[(size_t)HH * HH];     // c_proj_w^T hi : [2048][2048]
__device__ __nv_bfloat16 g_wp_lo[(size_t)HH * HH];

__device__ __forceinline__ uint32_t smem_u32(const void* p) {
    uint32_t a;
    asm("{ .reg .u64 t; cvta.to.shared.u64 t, %1; cvt.u32.u64 %0, t; }"
        : "=r"(a) : "l"(p));
    return a;
}

// ---------------- LayerNorm (writes bf16 hi/lo split) -----------------------
__global__ void __launch_bounds__(256) ln_kernel(
    const float* __restrict__ x, const float* __restrict__ w,
    const float* __restrict__ b,
    __nv_bfloat16* __restrict__ ohi, __nv_bfloat16* __restrict__ olo)
{
    int row = blockIdx.x;
    const float* xr = x + (size_t)row * HH;
    float v[8];
    float s = 0.f, s2 = 0.f;
    #pragma unroll
    for (int i = 0; i < 8; i++) {
        v[i] = xr[threadIdx.x + i * 256];
        s  += v[i];
        s2 += v[i] * v[i];
    }
    __shared__ float red0[8], red1[8];
    #pragma unroll
    for (int off = 16; off; off >>= 1) {
        s  += __shfl_xor_sync(0xffffffffu, s,  off);
        s2 += __shfl_xor_sync(0xffffffffu, s2, off);
    }
    int warp = threadIdx.x >> 5, lane = threadIdx.x & 31;
    if (lane == 0) { red0[warp] = s; red1[warp] = s2; }
    __syncthreads();
    if (warp == 0) {
        s  = red0[lane & 7];
        s2 = red1[lane & 7];
        #pragma unroll
        for (int off = 4; off; off >>= 1) {
            s  += __shfl_xor_sync(0xffffffffu, s,  off);
            s2 += __shfl_xor_sync(0xffffffffu, s2, off);
        }
        if (lane == 0) { red0[0] = s; red1[0] = s2; }
    }
    __syncthreads();
    float mu  = red0[0] * (1.f / HH);
    float var = red1[0] * (1.f / HH) - mu * mu;
    float rs  = rsqrtf(var + 1e-5f);
    size_t base = (size_t)row * HH;
    #pragma unroll
    for (int i = 0; i < 8; i++) {
        int c = threadIdx.x + i * 256;
        float y = (v[i] - mu) * rs * w[c] + b[c];
        __nv_bfloat16 hi = __float2bfloat16_rn(y);
        float lo = y - __bfloat162float(hi);
        ohi[base + c] = hi;
        olo[base + c] = __float2bfloat16_rn(lo);
    }
}

// ---------------- weight transpose + hi/lo split: in[K][N] -> out[N][K] -----
__global__ void __launch_bounds__(256) transpose_split_kernel(
    const float* __restrict__ in,
    __nv_bfloat16* __restrict__ ohi, __nv_bfloat16* __restrict__ olo,
    int K, int N)
{
    __shared__ float t[32][33];
    int n0 = blockIdx.x * 32, k0 = blockIdx.y * 32;
    int x = threadIdx.x & 31, y4 = (threadIdx.x >> 5) * 4;
    #pragma unroll
    for (int i = 0; i < 4; i++)
        t[y4 + i][x] = in[(size_t)(k0 + y4 + i) * N + n0 + x];
    __syncthreads();
    #pragma unroll
    for (int i = 0; i < 4; i++) {
        float vv = t[x][y4 + i];
        __nv_bfloat16 hi = __float2bfloat16_rn(vv);
        float lo = vv - __bfloat162float(hi);
        size_t idx = (size_t)(n0 + y4 + i) * K + k0 + x;
        ohi[idx] = hi;
        olo[idx] = __float2bfloat16_rn(lo);
    }
}

// ---------------- bf16x3 GEMM: C = Ahi@Whi^T + Ahi@Wlo^T + Alo@Whi^T --------
// Block tile 256(M) x 128(N), k-stage 32, 3-stage cp.async, 8 warps 64x64.
// mma.sync.m16n8k16.bf16 (2x tf32 rate). Products exact in fp32 accum;
// dropped lo@lo term ~2^-18 -> near-fp32 accuracy.
#define GA_ST 20480                       /* 256 rows * 80B (40 halfs) */
#define GB_ST 10240                       /* 128 rows * 80B */
#define GB_BASE (3 * GA_ST)               /* 61440 */
#define GEMM_SMEM (3 * (GA_ST + GB_ST))   /* 92160 */
#define SROW 20                           /* smem row stride in 32-bit words */

template<bool RES>
__global__ void __launch_bounds__(256, 1) gemm_bf3(
    const __nv_bfloat16* __restrict__ Ahi, const __nv_bfloat16* __restrict__ Alo,
    const __nv_bfloat16* __restrict__ Whi, const __nv_bfloat16* __restrict__ Wlo,
    const float* __restrict__ bias, const float* __restrict__ res,
    float* __restrict__ C, int M, int N, int K)
{
    extern __shared__ char smem[];
    uint32_t sb = smem_u32(smem);

    int tid  = threadIdx.x;
    int warp = tid >> 5, lane = tid & 31;
    int g = lane >> 2, t = lane & 3;
    int wm = (warp >> 1) * 64;
    int wn = (warp & 1) * 64;
    int bm = blockIdx.y * 256;
    int bn = blockIdx.x * 128;

    float acc[4][8][4];
    #pragma unroll
    for (int mi = 0; mi < 4; mi++)
        #pragma unroll
        for (int ni = 0; ni < 8; ni++)
            #pragma unroll
            for (int c = 0; c < 4; c++) acc[mi][ni][c] = 0.f;

    const int KTK = K >> 5;         // k-stages per term (64 for K=2048)
    const int KT  = 3 * KTK;        // total stages

    auto fill = [&](int kt) {
        int term = kt / KTK;                       // 0,1,2
        int kk = (kt - term * KTK) * 32;           // k offset (halfs)
        const __nv_bfloat16* Asrc = (term == 2) ? Alo : Ahi;
        const __nv_bfloat16* Bsrc = (term == 1) ? Wlo : Whi;
        int s = kt % 3;
        #pragma unroll
        for (int p = 0; p < 4; p++) {              // A: 1024 x 16B chunks
            int idx = tid + p * 256;
            int r = idx >> 2, c = idx & 3;
            uint32_t d = sb + s * GA_ST + r * 80 + c * 16;
            const __nv_bfloat16* src = Asrc + (size_t)(bm + r) * K + kk + c * 8;
            asm volatile("cp.async.cg.shared.global [%0], [%1], 16;" :: "r"(d), "l"(src) : "memory");
        }
        #pragma unroll
        for (int p = 0; p < 2; p++) {              // B: 512 x 16B chunks
            int idx = tid + p * 256;
            int r = idx >> 2, c = idx & 3;
            uint32_t d = sb + GB_BASE + s * GB_ST + r * 80 + c * 16;
            const __nv_bfloat16* src = Bsrc + (size_t)(bn + r) * K + kk + c * 8;
            asm volatile("cp.async.cg.shared.global [%0], [%1], 16;" :: "r"(d), "l"(src) : "memory");
        }
        asm volatile("cp.async.commit_group;" ::: "memory");
    };

    fill(0);
    fill(1);

    for (int kt = 0; kt < KT; kt++) {
        asm volatile("cp.async.wait_group 1;" ::: "memory");
        __syncthreads();                           // stage kt ready
        if (kt + 2 < KT) fill(kt + 2);

        int s = kt % 3;
        const uint32_t* Aw = (const uint32_t*)(smem + s * GA_ST);
        const uint32_t* Bw = (const uint32_t*)(smem + GB_BASE + s * GB_ST);

        #pragma unroll
        for (int ks = 0; ks < 2; ks++) {           // two k16 steps per stage
            int kw = ks * 8;                       // word offset within row
            uint32_t af[4][4], bf[8][2];
            #pragma unroll
            for (int mi = 0; mi < 4; mi++) {
                int r0 = (wm + mi * 16 + g) * SROW + kw;
                int r1 = r0 + 8 * SROW;
                af[mi][0] = Aw[r0 + t];            // (row g,    k 2t..2t+1)
                af[mi][1] = Aw[r1 + t];            // (row g+8)
                af[mi][2] = Aw[r0 + t + 4];        // (row g,    k 8+2t..)
                af[mi][3] = Aw[r1 + t + 4];
            }
            #pragma unroll
            for (int ni = 0; ni < 8; ni++) {
                int nb = (wn + ni * 8 + g) * SROW + kw;
                bf[ni][0] = Bw[nb + t];
                bf[ni][1] = Bw[nb + t + 4];
            }
            #pragma unroll
            for (int mi = 0; mi < 4; mi++)
                #pragma unroll
                for (int ni = 0; ni < 8; ni++)
                    asm volatile(
                        "mma.sync.aligned.m16n8k16.row.col.f32.bf16.bf16.f32 "
                        "{%0,%1,%2,%3},{%4,%5,%6,%7},{%8,%9},{%0,%1,%2,%3};"
                        : "+f"(acc[mi][ni][0]), "+f"(acc[mi][ni][1]),
                          "+f"(acc[mi][ni][2]), "+f"(acc[mi][ni][3])
                        : "r"(af[mi][0]), "r"(af[mi][1]), "r"(af[mi][2]), "r"(af[mi][3]),
                          "r"(bf[ni][0]), "r"(bf[ni][1]));
        }
    }

    // ---- epilogue
    #pragma unroll
    for (int mi = 0; mi < 4; mi++) {
        int r0 = bm + wm + mi * 16 + g;
        #pragma unroll
        for (int ni = 0; ni < 8; ni++) {
            int c0 = bn + wn + ni * 8 + 2 * t;
            #pragma unroll
            for (int half = 0; half < 2; half++) {
                int row = r0 + half * 8;
                float2 v;
                v.x = acc[mi][ni][half * 2 + 0] + bias[c0];
                v.y = acc[mi][ni][half * 2 + 1] + bias[c0 + 1];
                if (RES) {
                    float2 rr = *(const float2*)(res + (size_t)row * N + c0);
                    v.x += rr.x; v.y += rr.y;
                }
                *(float2*)(C + (size_t)row * N + c0) = v;
            }
        }
    }
}

// ---------------- tensor-core (tf32) flash attention ------------------------
#define BLKQ 128
#define BLKK 64
#define FSTR 136
#define KVSZ (BLKK * FSTR)
#define FLASH_SMEM ((BLKQ * FSTR + 4 * KVSZ) * (int)sizeof(float))  /* 208896 B */

__global__ void __launch_bounds__(256) flash_tc_kernel(
    const float* __restrict__ qkv,
    __nv_bfloat16* __restrict__ ohi, __nv_bfloat16* __restrict__ olo)
{
    extern __shared__ float sm[];
    float* Qs = sm;                         // [128][FSTR]
    float* KV = sm + BLKQ * FSTR;           // 2 x (K[64][FSTR], V[64][FSTR])

    int tid  = threadIdx.x;
    int warp = tid >> 5, lane = tid & 31;
    int g = lane >> 2, t = lane & 3;
    int qt = 15 - (int)blockIdx.x;          // heavy tiles first
    int bh = blockIdx.y;
    int b = bh >> 4, h = bh & 15;
    int q0 = qt * BLKQ;
    size_t rowbase = (size_t)b * SS;
    size_t hoff = (size_t)h * 128;
    const float scale = 0.08838834764831845f;   // 1/sqrt(128)

    // ---- load Q (scaled) into smem
    #pragma unroll
    for (int i = 0; i < 16; i++) {
        int idx = tid + i * 256;            // 4096 float4s
        int r = idx >> 5, c4 = (idx & 31) * 4;
        float4 v = *(const float4*)(qkv + (rowbase + q0 + r) * QKVN + hoff + c4);
        float* d = Qs + r * FSTR + c4;
        d[0] = v.x * scale; d[1] = v.y * scale;
        d[2] = v.z * scale; d[3] = v.w * scale;
    }

    auto issue_tile = [&](int kt) {
        int kb = kt * BLKK;
        float* Kb = KV + (kt & 1) * 2 * KVSZ;
        float* Vb = Kb + KVSZ;
        #pragma unroll
        for (int i = 0; i < 8; i++) {
            int idx = tid + i * 256;        // 2048 float4s per operand
            int r = idx >> 5, c4 = (idx & 31) * 4;
            const float* gk = qkv + (rowbase + kb + r) * QKVN + hoff + 2048 + c4;
            const float* gv = gk + 2048;
            uint32_t sk = smem_u32(Kb + r * FSTR + c4);
            uint32_t sv = smem_u32(Vb + r * FSTR + c4);
            asm volatile("cp.async.cg.shared.global [%0], [%1], 16;" :: "r"(sk), "l"(gk) : "memory");
            asm volatile("cp.async.cg.shared.global [%0], [%1], 16;" :: "r"(sv), "l"(gv) : "memory");
        }
        asm volatile("cp.async.commit_group;" ::: "memory");
    };

    float m0 = -1e30f, m1 = -1e30f, l0 = 0.f, l1 = 0.f;
    float oa[16][4];
    #pragma unroll
    for (int nt = 0; nt < 16; nt++)
        #pragma unroll
        for (int c = 0; c < 4; c++) oa[nt][c] = 0.f;

    const int NKT = (q0 + BLKQ) / BLKK;     // 2*qt + 2
    const int myrow0 = q0 + warp * 16;      // first q row of this warp
    const int arow0 = (warp * 16 + g) * FSTR;
    const int arow1 = arow0 + 8 * FSTR;

    issue_tile(0);

    for (int kt = 0; kt < NKT; kt++) {
        int kb = kt * BLKK;
        asm volatile("cp.async.wait_group 0;" ::: "memory");
        __syncthreads();                     // tile kt visible; prev tile's bufs free
        if (kt + 1 < NKT) issue_tile(kt + 1);

        bool active = (kb <= myrow0 + 15);   // warp-uniform
        float* Kb = KV + (kt & 1) * 2 * KVSZ;
        float* Vb = Kb + KVSZ;

        if (active) {
            // ---- S = Q @ K^T  (128 mmas/warp)
            float s[8][4];
            #pragma unroll
            for (int n = 0; n < 8; n++)
                #pragma unroll
                for (int c = 0; c < 4; c++) s[n][c] = 0.f;

            #pragma unroll
            for (int k = 0; k < 16; k++) {
                int k0 = k * 8;
                uint32_t a0 = __float_as_uint(Qs[arow0 + k0 + t]);
                uint32_t a1 = __float_as_uint(Qs[arow1 + k0 + t]);
                uint32_t a2 = __float_as_uint(Qs[arow0 + k0 + t + 4]);
                uint32_t a3 = __float_as_uint(Qs[arow1 + k0 + t + 4]);
                #pragma unroll
                for (int n = 0; n < 8; n++) {
                    uint32_t b0 = __float_as_uint(Kb[(n * 8 + g) * FSTR + k0 + t]);
                    uint32_t b1 = __float_as_uint(Kb[(n * 8 + g) * FSTR + k0 + t + 4]);
                    asm volatile(
                        "mma.sync.aligned.m16n8k8.row.col.f32.tf32.tf32.f32 "
                        "{%0,%1,%2,%3},{%4,%5,%6,%7},{%8,%9},{%0,%1,%2,%3};"
                        : "+f"(s[n][0]), "+f"(s[n][1]), "+f"(s[n][2]), "+f"(s[n][3])
                        : "r"(a0), "r"(a1), "r"(a2), "r"(a3), "r"(b0), "r"(b1));
                }
            }

            // ---- causal mask (only tiles straddling this warp's diagonal)
            if (kb + BLKK - 1 > myrow0) {
                int r0 = myrow0 + g, r1 = r0 + 8;
                #pragma unroll
                for (int n = 0; n < 8; n++) {
                    int c = kb + n * 8 + 2 * t;
                    if (c     > r0) s[n][0] = -1e30f;
                    if (c + 1 > r0) s[n][1] = -1e30f;
                    if (c     > r1) s[n][2] = -1e30f;
                    if (c + 1 > r1) s[n][3] = -1e30f;
                }
            }

            // ---- online softmax (rows g and g+8)
            float mx0 = -1e30f, mx1 = -1e30f;
            #pragma unroll
            for (int n = 0; n < 8; n++) {
                mx0 = fmaxf(mx0, fmaxf(s[n][0], s[n][1]));
                mx1 = fmaxf(mx1, fmaxf(s[n][2], s[n][3]));
            }
            mx0 = fmaxf(mx0, __shfl_xor_sync(0xffffffffu, mx0, 1));
            mx0 = fmaxf(mx0, __shfl_xor_sync(0xffffffffu, mx0, 2));
            mx1 = fmaxf(mx1, __shfl_xor_sync(0xffffffffu, mx1, 1));
            mx1 = fmaxf(mx1, __shfl_xor_sync(0xffffffffu, mx1, 2));
            float mn0 = fmaxf(m0, mx0), mn1 = fmaxf(m1, mx1);
            float al0 = __expf(m0 - mn0), al1 = __expf(m1 - mn1);
            float ls0 = 0.f, ls1 = 0.f;
            #pragma unroll
            for (int n = 0; n < 8; n++) {
                s[n][0] = __expf(s[n][0] - mn0);
                s[n][1] = __expf(s[n][1] - mn0);
                s[n][2] = __expf(s[n][2] - mn1);
                s[n][3] = __expf(s[n][3] - mn1);
                ls0 += s[n][0] + s[n][1];
                ls1 += s[n][2] + s[n][3];
            }
            ls0 += __shfl_xor_sync(0xffffffffu, ls0, 1);
            ls0 += __shfl_xor_sync(0xffffffffu, ls0, 2);
            ls1 += __shfl_xor_sync(0xffffffffu, ls1, 1);
            ls1 += __shfl_xor_sync(0xffffffffu, ls1, 2);
            l0 = l0 * al0 + ls0;  l1 = l1 * al1 + ls1;
            m0 = mn0;  m1 = mn1;
            #pragma unroll
            for (int nt = 0; nt < 16; nt++) {
                oa[nt][0] *= al0; oa[nt][1] *= al0;
                oa[nt][2] *= al1; oa[nt][3] *= al1;
            }

            // ---- O += P @ V  (P C-frag -> A-frag via quad shuffles)
            int src0 = (g << 2) | (t >> 1);
            int src1 = src0 + 2;
            bool odd = (t & 1);
            #pragma unroll
            for (int j = 0; j < 8; j++) {
                float x0 = __shfl_sync(0xffffffffu, s[j][0], src0);
                float y0 = __shfl_sync(0xffffffffu, s[j][1], src0);
                float x1 = __shfl_sync(0xffffffffu, s[j][0], src1);
                float y1 = __shfl_sync(0xffffffffu, s[j][1], src1);
                float x2 = __shfl_sync(0xffffffffu, s[j][2], src0);
                float y2 = __shfl_sync(0xffffffffu, s[j][3], src0);
                float x3 = __shfl_sync(0xffffffffu, s[j][2], src1);
                float y3 = __shfl_sync(0xffffffffu, s[j][3], src1);
                uint32_t a0 = __float_as_uint(odd ? y0 : x0);   // P[g   ][8j+t  ]
                uint32_t a1 = __float_as_uint(odd ? y2 : x2);   // P[g+8 ][8j+t  ]
                uint32_t a2 = __float_as_uint(odd ? y1 : x1);   // P[g   ][8j+t+4]
                uint32_t a3 = __float_as_uint(odd ? y3 : x3);   // P[g+8 ][8j+t+4]
                #pragma unroll
                for (int nt = 0; nt < 16; nt++) {
                    uint32_t b0 = __float_as_uint(Vb[(j * 8 + t)     * FSTR + nt * 8 + g]);
                    uint32_t b1 = __float_as_uint(Vb[(j * 8 + t + 4) * FSTR + nt * 8 + g]);
                    asm volatile(
                        "mma.sync.aligned.m16n8k8.row.col.f32.tf32.tf32.f32 "
                        "{%0,%1,%2,%3},{%4,%5,%6,%7},{%8,%9},{%0,%1,%2,%3};"
                        : "+f"(oa[nt][0]), "+f"(oa[nt][1]), "+f"(oa[nt][2]), "+f"(oa[nt][3])
                        : "r"(a0), "r"(a1), "r"(a2), "r"(a3), "r"(b0), "r"(b1));
                }
            }
        }
    }

    // ---- epilogue: normalize, hi/lo split, store bf16
    float inv0 = 1.0f / l0, inv1 = 1.0f / l1;
    int r0 = q0 + warp * 16 + g;
    size_t ob0 = (rowbase + r0) * HH + hoff;
    size_t ob1 = ob0 + (size_t)8 * HH;
    #pragma unroll
    for (int nt = 0; nt < 16; nt++) {
        int col = nt * 8 + 2 * t;
        float v00 = oa[nt][0] * inv0, v01 = oa[nt][1] * inv0;
        float v10 = oa[nt][2] * inv1, v11 = oa[nt][3] * inv1;
        __nv_bfloat16 h00 = __float2bfloat16_rn(v00);
        __nv_bfloat16 h01 = __float2bfloat16_rn(v01);
        __nv_bfloat16 h10 = __float2bfloat16_rn(v10);
        __nv_bfloat16 h11 = __float2bfloat16_rn(v11);
        __nv_bfloat162 ph0, ph1, pl0, pl1;
        ph0.x = h00; ph0.y = h01;
        ph1.x = h10; ph1.y = h11;
        pl0.x = __float2bfloat16_rn(v00 - __bfloat162float(h00));
        pl0.y = __float2bfloat16_rn(v01 - __bfloat162float(h01));
        pl1.x = __float2bfloat16_rn(v10 - __bfloat162float(h10));
        pl1.y = __float2bfloat16_rn(v11 - __bfloat162float(h11));
        *(__nv_bfloat162*)(ohi + ob0 + col) = ph0;
        *(__nv_bfloat162*)(ohi + ob1 + col) = ph1;
        *(__nv_bfloat162*)(olo + ob0 + col) = pl0;
        *(__nv_bfloat162*)(olo + ob1 + col) = pl1;
    }
}

// ---------------- launch ----------------------------------------------------
extern "C" void kernel_launch(void* const* d_in, const int* in_sizes, int n_in,
                              void* d_out, int out_size)
{
    const float* x        = (const float*)d_in[0];
    const float* ln_w     = (const float*)d_in[1];
    const float* ln_b     = (const float*)d_in[2];
    const float* c_attn_w = (const float*)d_in[3];
    const float* c_attn_b = (const float*)d_in[4];
    const float* c_proj_w = (const float*)d_in[5];
    const float* c_proj_b = (const float*)d_in[6];
    float* out = (float*)d_out;

    void *p_xh, *p_xl, *p_qkv, *p_oh, *p_ol, *p_wah, *p_wal, *p_wph, *p_wpl;
    cudaGetSymbolAddress(&p_xh,  g_xn_hi);
    cudaGetSymbolAddress(&p_xl,  g_xn_lo);
    cudaGetSymbolAddress(&p_qkv, g_qkv);
    cudaGetSymbolAddress(&p_oh,  g_o_hi);
    cudaGetSymbolAddress(&p_ol,  g_o_lo);
    cudaGetSymbolAddress(&p_wah, g_wa_hi);
    cudaGetSymbolAddress(&p_wal, g_wa_lo);
    cudaGetSymbolAddress(&p_wph, g_wp_hi);
    cudaGetSymbolAddress(&p_wpl, g_wp_lo);
    __nv_bfloat16* xnh = (__nv_bfloat16*)p_xh;
    __nv_bfloat16* xnl = (__nv_bfloat16*)p_xl;
    float* qkv = (float*)p_qkv;
    __nv_bfloat16* oh  = (__nv_bfloat16*)p_oh;
    __nv_bfloat16* ol  = (__nv_bfloat16*)p_ol;
    __nv_bfloat16* wah = (__nv_bfloat16*)p_wah;
    __nv_bfloat16* wal = (__nv_bfloat16*)p_wal;
    __nv_bfloat16* wph = (__nv_bfloat16*)p_wph;
    __nv_bfloat16* wpl = (__nv_bfloat16*)p_wpl;

    cudaFuncSetAttribute(gemm_bf3<false>,
                         cudaFuncAttributeMaxDynamicSharedMemorySize, GEMM_SMEM);
    cudaFuncSetAttribute(gemm_bf3<true>,
                         cudaFuncAttributeMaxDynamicSharedMemorySize, GEMM_SMEM);
    cudaFuncSetAttribute(flash_tc_kernel,
                         cudaFuncAttributeMaxDynamicSharedMemorySize, FLASH_SMEM);

    // 0. transpose + split weights to bf16 hi/lo [N][K]
    transpose_split_kernel<<<dim3(QKVN / 32, HH / 32), 256>>>(c_attn_w, wah, wal, HH, QKVN);
    transpose_split_kernel<<<dim3(HH / 32, HH / 32), 256>>>(c_proj_w, wph, wpl, HH, HH);

    // 1. LayerNorm (fused bf16 hi/lo split)
    ln_kernel<<<MROWS, 256>>>(x, ln_w, ln_b, xnh, xnl);

    // 2. QKV projection: [8192,2048] @ [2048,6144] + bias   (bf16x3)
    gemm_bf3<false><<<dim3(QKVN / 128, MROWS / 256), 256, GEMM_SMEM>>>(
        xnh, xnl, wah, wal, c_attn_b, nullptr, qkv, MROWS, QKVN, HH);

    // 3. causal flash attention (tf32 tensor cores), writes bf16 hi/lo O
    flash_tc_kernel<<<dim3(SS / BLKQ, BB * NHH), 256, FLASH_SMEM>>>(qkv, oh, ol);

    // 4. output projection + bias + residual   (bf16x3)
    gemm_bf3<true><<<dim3(HH / 128, MROWS / 256), 256, GEMM_SMEM>>>(
        oh, ol, wph, wpl, c_proj_b, x, out, MROWS, HH, HH);
}

// round 11
// speedup vs baseline: 2.2449x; 2.2449x over previous
#include <cuda_runtime.h>
#include <cuda_fp16.h>
#include <cstdint>

#define BB 4
#define SS 2048
#define HH 2048
#define NHH 16
#define HDD 128
#define MROWS (BB*SS)      /* 8192 */
#define QKVN (3*HH)        /* 6144 */

// ---------------- scratch (static device allocations are allowed) ----------
__device__ __half g_xn[(size_t)MROWS * HH];
__device__ float  g_qkv[(size_t)MROWS * QKVN];
__device__ __half g_o [(size_t)MROWS * HH];
__device__ __half g_wa[(size_t)QKVN * HH];   // c_attn_w^T : [6144][2048] fp16
__device__ __half g_wp[(size_t)HH * HH];     // c_proj_w^T : [2048][2048] fp16

__device__ __forceinline__ uint32_t smem_u32(const void* p) {
    uint32_t a;
    asm("{ .reg .u64 t; cvta.to.shared.u64 t, %1; cvt.u32.u64 %0, t; }"
        : "=r"(a) : "l"(p));
    return a;
}

// ---------------- LayerNorm (writes fp16) -----------------------------------
__global__ void __launch_bounds__(256) ln_kernel(
    const float* __restrict__ x, const float* __restrict__ w,
    const float* __restrict__ b, __half* __restrict__ out)
{
    int row = blockIdx.x;
    const float* xr = x + (size_t)row * HH;
    float v[8];
    float s = 0.f, s2 = 0.f;
    #pragma unroll
    for (int i = 0; i < 8; i++) {
        v[i] = xr[threadIdx.x + i * 256];
        s  += v[i];
        s2 += v[i] * v[i];
    }
    __shared__ float red0[8], red1[8];
    #pragma unroll
    for (int off = 16; off; off >>= 1) {
        s  += __shfl_xor_sync(0xffffffffu, s,  off);
        s2 += __shfl_xor_sync(0xffffffffu, s2, off);
    }
    int warp = threadIdx.x >> 5, lane = threadIdx.x & 31;
    if (lane == 0) { red0[warp] = s; red1[warp] = s2; }
    __syncthreads();
    if (warp == 0) {
        s  = red0[lane & 7];
        s2 = red1[lane & 7];
        #pragma unroll
        for (int off = 4; off; off >>= 1) {
            s  += __shfl_xor_sync(0xffffffffu, s,  off);
            s2 += __shfl_xor_sync(0xffffffffu, s2, off);
        }
        if (lane == 0) { red0[0] = s; red1[0] = s2; }
    }
    __syncthreads();
    float mu  = red0[0] * (1.f / HH);
    float var = red1[0] * (1.f / HH) - mu * mu;
    float rs  = rsqrtf(var + 1e-5f);
    size_t base = (size_t)row * HH;
    #pragma unroll
    for (int i = 0; i < 8; i++) {
        int c = threadIdx.x + i * 256;
        out[base + c] = __float2half_rn((v[i] - mu) * rs * w[c] + b[c]);
    }
}

// ---------------- weight transpose + fp16 cast: in[K][N] -> out[N][K] -------
__global__ void __launch_bounds__(256) transpose_h_kernel(
    const float* __restrict__ in, __half* __restrict__ out, int K, int N)
{
    __shared__ float t[32][33];
    int n0 = blockIdx.x * 32, k0 = blockIdx.y * 32;
    int x = threadIdx.x & 31, y4 = (threadIdx.x >> 5) * 4;
    #pragma unroll
    for (int i = 0; i < 4; i++)
        t[y4 + i][x] = in[(size_t)(k0 + y4 + i) * N + n0 + x];
    __syncthreads();
    #pragma unroll
    for (int i = 0; i < 4; i++)
        out[(size_t)(n0 + y4 + i) * K + k0 + x] = __float2half_rn(t[x][y4 + i]);
}

// ---------------- fp16 GEMM: C[M,N] = A[M,K] @ W[N,K]^T + bias [+res] -------
// Block tile 256(M) x 128(N), k-stage 32, 3-stage cp.async, 8 warps 64x64.
// mma.sync.m16n8k16.f16 (fp32 accum) — same 11-bit precision as tf32, ~2x rate.
#define GA_ST 20480                       /* 256 rows * 80B (40 halfs) */
#define GB_ST 10240                       /* 128 rows * 80B */
#define GB_BASE (3 * GA_ST)               /* 61440 */
#define GEMM_SMEM (3 * (GA_ST + GB_ST))   /* 92160 */
#define SROW 20                           /* smem row stride in 32-bit words */

template<bool RES>
__global__ void __launch_bounds__(256, 1) gemm_f16(
    const __half* __restrict__ A, const __half* __restrict__ W,
    const float* __restrict__ bias, const float* __restrict__ res,
    float* __restrict__ C, int M, int N, int K)
{
    extern __shared__ char smem[];
    uint32_t sb = smem_u32(smem);

    int tid  = threadIdx.x;
    int warp = tid >> 5, lane = tid & 31;
    int g = lane >> 2, t = lane & 3;
    int wm = (warp >> 1) * 64;
    int wn = (warp & 1) * 64;
    int bm = blockIdx.y * 256;
    int bn = blockIdx.x * 128;

    float acc[4][8][4];
    #pragma unroll
    for (int mi = 0; mi < 4; mi++)
        #pragma unroll
        for (int ni = 0; ni < 8; ni++)
            #pragma unroll
            for (int c = 0; c < 4; c++) acc[mi][ni][c] = 0.f;

    const int KT = K >> 5;          // 64 stages of k=32

    auto fill = [&](int kt) {
        int kk = kt * 32;
        int s = kt % 3;
        #pragma unroll
        for (int p = 0; p < 4; p++) {              // A: 1024 x 16B chunks
            int idx = tid + p * 256;
            int r = idx >> 2, c = idx & 3;
            uint32_t d = sb + s * GA_ST + r * 80 + c * 16;
            const __half* src = A + (size_t)(bm + r) * K + kk + c * 8;
            asm volatile("cp.async.cg.shared.global [%0], [%1], 16;" :: "r"(d), "l"(src) : "memory");
        }
        #pragma unroll
        for (int p = 0; p < 2; p++) {              // B: 512 x 16B chunks
            int idx = tid + p * 256;
            int r = idx >> 2, c = idx & 3;
            uint32_t d = sb + GB_BASE + s * GB_ST + r * 80 + c * 16;
            const __half* src = W + (size_t)(bn + r) * K + kk + c * 8;
            asm volatile("cp.async.cg.shared.global [%0], [%1], 16;" :: "r"(d), "l"(src) : "memory");
        }
        asm volatile("cp.async.commit_group;" ::: "memory");
    };

    fill(0);
    fill(1);

    for (int kt = 0; kt < KT; kt++) {
        asm volatile("cp.async.wait_group 1;" ::: "memory");
        __syncthreads();                           // stage kt ready
        if (kt + 2 < KT) fill(kt + 2);

        int s = kt % 3;
        const uint32_t* Aw = (const uint32_t*)(smem + s * GA_ST);
        const uint32_t* Bw = (const uint32_t*)(smem + GB_BASE + s * GB_ST);

        #pragma unroll
        for (int ks = 0; ks < 2; ks++) {           // two k16 steps per stage
            int kw = ks * 8;                       // word offset within row
            uint32_t af[4][4], bf[8][2];
            #pragma unroll
            for (int mi = 0; mi < 4; mi++) {
                int r0 = (wm + mi * 16 + g) * SROW + kw;
                int r1 = r0 + 8 * SROW;
                af[mi][0] = Aw[r0 + t];            // (row g,   k 2t..2t+1)
                af[mi][1] = Aw[r1 + t];            // (row g+8)
                af[mi][2] = Aw[r0 + t + 4];        // (row g,   k 8+2t..)
                af[mi][3] = Aw[r1 + t + 4];
            }
            #pragma unroll
            for (int ni = 0; ni < 8; ni++) {
                int nb = (wn + ni * 8 + g) * SROW + kw;
                bf[ni][0] = Bw[nb + t];
                bf[ni][1] = Bw[nb + t + 4];
            }
            #pragma unroll
            for (int mi = 0; mi < 4; mi++)
                #pragma unroll
                for (int ni = 0; ni < 8; ni++)
                    asm volatile(
                        "mma.sync.aligned.m16n8k16.row.col.f32.f16.f16.f32 "
                        "{%0,%1,%2,%3},{%4,%5,%6,%7},{%8,%9},{%0,%1,%2,%3};"
                        : "+f"(acc[mi][ni][0]), "+f"(acc[mi][ni][1]),
                          "+f"(acc[mi][ni][2]), "+f"(acc[mi][ni][3])
                        : "r"(af[mi][0]), "r"(af[mi][1]), "r"(af[mi][2]), "r"(af[mi][3]),
                          "r"(bf[ni][0]), "r"(bf[ni][1]));
        }
    }

    // ---- epilogue
    #pragma unroll
    for (int mi = 0; mi < 4; mi++) {
        int r0 = bm + wm + mi * 16 + g;
        #pragma unroll
        for (int ni = 0; ni < 8; ni++) {
            int c0 = bn + wn + ni * 8 + 2 * t;
            #pragma unroll
            for (int half_ = 0; half_ < 2; half_++) {
                int row = r0 + half_ * 8;
                float2 v;
                v.x = acc[mi][ni][half_ * 2 + 0] + bias[c0];
                v.y = acc[mi][ni][half_ * 2 + 1] + bias[c0 + 1];
                if (RES) {
                    float2 rr = *(const float2*)(res + (size_t)row * N + c0);
                    v.x += rr.x; v.y += rr.y;
                }
                *(float2*)(C + (size_t)row * N + c0) = v;
            }
        }
    }
}

// ---------------- tensor-core (tf32) flash attention ------------------------
#define BLKQ 128
#define BLKK 64
#define FSTR 136
#define KVSZ (BLKK * FSTR)
#define FLASH_SMEM ((BLKQ * FSTR + 4 * KVSZ) * (int)sizeof(float))  /* 208896 B */

__global__ void __launch_bounds__(256) flash_tc_kernel(
    const float* __restrict__ qkv, __half* __restrict__ o)
{
    extern __shared__ float sm[];
    float* Qs = sm;                         // [128][FSTR]
    float* KV = sm + BLKQ * FSTR;           // 2 x (K[64][FSTR], V[64][FSTR])

    int tid  = threadIdx.x;
    int warp = tid >> 5, lane = tid & 31;
    int g = lane >> 2, t = lane & 3;
    int qt = 15 - (int)blockIdx.x;          // heavy tiles first
    int bh = blockIdx.y;
    int b = bh >> 4, h = bh & 15;
    int q0 = qt * BLKQ;
    size_t rowbase = (size_t)b * SS;
    size_t hoff = (size_t)h * 128;
    const float scale = 0.08838834764831845f;   // 1/sqrt(128)

    // ---- load Q (scaled) into smem
    #pragma unroll
    for (int i = 0; i < 16; i++) {
        int idx = tid + i * 256;            // 4096 float4s
        int r = idx >> 5, c4 = (idx & 31) * 4;
        float4 v = *(const float4*)(qkv + (rowbase + q0 + r) * QKVN + hoff + c4);
        float* d = Qs + r * FSTR + c4;
        d[0] = v.x * scale; d[1] = v.y * scale;
        d[2] = v.z * scale; d[3] = v.w * scale;
    }

    auto issue_tile = [&](int kt) {
        int kb = kt * BLKK;
        float* Kb = KV + (kt & 1) * 2 * KVSZ;
        float* Vb = Kb + KVSZ;
        #pragma unroll
        for (int i = 0; i < 8; i++) {
            int idx = tid + i * 256;        // 2048 float4s per operand
            int r = idx >> 5, c4 = (idx & 31) * 4;
            const float* gk = qkv + (rowbase + kb + r) * QKVN + hoff + 2048 + c4;
            const float* gv = gk + 2048;
            uint32_t sk = smem_u32(Kb + r * FSTR + c4);
            uint32_t sv = smem_u32(Vb + r * FSTR + c4);
            asm volatile("cp.async.cg.shared.global [%0], [%1], 16;" :: "r"(sk), "l"(gk) : "memory");
            asm volatile("cp.async.cg.shared.global [%0], [%1], 16;" :: "r"(sv), "l"(gv) : "memory");
        }
        asm volatile("cp.async.commit_group;" ::: "memory");
    };

    float m0 = -1e30f, m1 = -1e30f, l0 = 0.f, l1 = 0.f;
    float oa[16][4];
    #pragma unroll
    for (int nt = 0; nt < 16; nt++)
        #pragma unroll
        for (int c = 0; c < 4; c++) oa[nt][c] = 0.f;

    const int NKT = (q0 + BLKQ) / BLKK;     // 2*qt + 2
    const int myrow0 = q0 + warp * 16;      // first q row of this warp
    const int arow0 = (warp * 16 + g) * FSTR;
    const int arow1 = arow0 + 8 * FSTR;

    issue_tile(0);

    for (int kt = 0; kt < NKT; kt++) {
        int kb = kt * BLKK;
        asm volatile("cp.async.wait_group 0;" ::: "memory");
        __syncthreads();                     // tile kt visible; prev tile's bufs free
        if (kt + 1 < NKT) issue_tile(kt + 1);

        bool active = (kb <= myrow0 + 15);   // warp-uniform
        float* Kb = KV + (kt & 1) * 2 * KVSZ;
        float* Vb = Kb + KVSZ;

        if (active) {
            // ---- S = Q @ K^T  (128 mmas/warp)
            float s[8][4];
            #pragma unroll
            for (int n = 0; n < 8; n++)
                #pragma unroll
                for (int c = 0; c < 4; c++) s[n][c] = 0.f;

            #pragma unroll
            for (int k = 0; k < 16; k++) {
                int k0 = k * 8;
                uint32_t a0 = __float_as_uint(Qs[arow0 + k0 + t]);
                uint32_t a1 = __float_as_uint(Qs[arow1 + k0 + t]);
                uint32_t a2 = __float_as_uint(Qs[arow0 + k0 + t + 4]);
                uint32_t a3 = __float_as_uint(Qs[arow1 + k0 + t + 4]);
                #pragma unroll
                for (int n = 0; n < 8; n++) {
                    uint32_t b0 = __float_as_uint(Kb[(n * 8 + g) * FSTR + k0 + t]);
                    uint32_t b1 = __float_as_uint(Kb[(n * 8 + g) * FSTR + k0 + t + 4]);
                    asm volatile(
                        "mma.sync.aligned.m16n8k8.row.col.f32.tf32.tf32.f32 "
                        "{%0,%1,%2,%3},{%4,%5,%6,%7},{%8,%9},{%0,%1,%2,%3};"
                        : "+f"(s[n][0]), "+f"(s[n][1]), "+f"(s[n][2]), "+f"(s[n][3])
                        : "r"(a0), "r"(a1), "r"(a2), "r"(a3), "r"(b0), "r"(b1));
                }
            }

            // ---- causal mask (only tiles straddling this warp's diagonal)
            if (kb + BLKK - 1 > myrow0) {
                int r0 = myrow0 + g, r1 = r0 + 8;
                #pragma unroll
                for (int n = 0; n < 8; n++) {
                    int c = kb + n * 8 + 2 * t;
                    if (c     > r0) s[n][0] = -1e30f;
                    if (c + 1 > r0) s[n][1] = -1e30f;
                    if (c     > r1) s[n][2] = -1e30f;
                    if (c + 1 > r1) s[n][3] = -1e30f;
                }
            }

            // ---- online softmax (rows g and g+8)
            float mx0 = -1e30f, mx1 = -1e30f;
            #pragma unroll
            for (int n = 0; n < 8; n++) {
                mx0 = fmaxf(mx0, fmaxf(s[n][0], s[n][1]));
                mx1 = fmaxf(mx1, fmaxf(s[n][2], s[n][3]));
            }
            mx0 = fmaxf(mx0, __shfl_xor_sync(0xffffffffu, mx0, 1));
            mx0 = fmaxf(mx0, __shfl_xor_sync(0xffffffffu, mx0, 2));
            mx1 = fmaxf(mx1, __shfl_xor_sync(0xffffffffu, mx1, 1));
            mx1 = fmaxf(mx1, __shfl_xor_sync(0xffffffffu, mx1, 2));
            float mn0 = fmaxf(m0, mx0), mn1 = fmaxf(m1, mx1);
            float al0 = __expf(m0 - mn0), al1 = __expf(m1 - mn1);
            float ls0 = 0.f, ls1 = 0.f;
            #pragma unroll
            for (int n = 0; n < 8; n++) {
                s[n][0] = __expf(s[n][0] - mn0);
                s[n][1] = __expf(s[n][1] - mn0);
                s[n][2] = __expf(s[n][2] - mn1);
                s[n][3] = __expf(s[n][3] - mn1);
                ls0 += s[n][0] + s[n][1];
                ls1 += s[n][2] + s[n][3];
            }
            ls0 += __shfl_xor_sync(0xffffffffu, ls0, 1);
            ls0 += __shfl_xor_sync(0xffffffffu, ls0, 2);
            ls1 += __shfl_xor_sync(0xffffffffu, ls1, 1);
            ls1 += __shfl_xor_sync(0xffffffffu, ls1, 2);
            l0 = l0 * al0 + ls0;  l1 = l1 * al1 + ls1;
            m0 = mn0;  m1 = mn1;
            #pragma unroll
            for (int nt = 0; nt < 16; nt++) {
                oa[nt][0] *= al0; oa[nt][1] *= al0;
                oa[nt][2] *= al1; oa[nt][3] *= al1;
            }

            // ---- O += P @ V  (P C-frag -> A-frag via quad shuffles)
            int src0 = (g << 2) | (t >> 1);
            int src1 = src0 + 2;
            bool odd = (t & 1);
            #pragma unroll
            for (int j = 0; j < 8; j++) {
                float x0 = __shfl_sync(0xffffffffu, s[j][0], src0);
                float y0 = __shfl_sync(0xffffffffu, s[j][1], src0);
                float x1 = __shfl_sync(0xffffffffu, s[j][0], src1);
                float y1 = __shfl_sync(0xffffffffu, s[j][1], src1);
                float x2 = __shfl_sync(0xffffffffu, s[j][2], src0);
                float y2 = __shfl_sync(0xffffffffu, s[j][3], src0);
                float x3 = __shfl_sync(0xffffffffu, s[j][2], src1);
                float y3 = __shfl_sync(0xffffffffu, s[j][3], src1);
                uint32_t a0 = __float_as_uint(odd ? y0 : x0);   // P[g   ][8j+t  ]
                uint32_t a1 = __float_as_uint(odd ? y2 : x2);   // P[g+8 ][8j+t  ]
                uint32_t a2 = __float_as_uint(odd ? y1 : x1);   // P[g   ][8j+t+4]
                uint32_t a3 = __float_as_uint(odd ? y3 : x3);   // P[g+8 ][8j+t+4]
                #pragma unroll
                for (int nt = 0; nt < 16; nt++) {
                    uint32_t b0 = __float_as_uint(Vb[(j * 8 + t)     * FSTR + nt * 8 + g]);
                    uint32_t b1 = __float_as_uint(Vb[(j * 8 + t + 4) * FSTR + nt * 8 + g]);
                    asm volatile(
                        "mma.sync.aligned.m16n8k8.row.col.f32.tf32.tf32.f32 "
                        "{%0,%1,%2,%3},{%4,%5,%6,%7},{%8,%9},{%0,%1,%2,%3};"
                        : "+f"(oa[nt][0]), "+f"(oa[nt][1]), "+f"(oa[nt][2]), "+f"(oa[nt][3])
                        : "r"(a0), "r"(a1), "r"(a2), "r"(a3), "r"(b0), "r"(b1));
                }
            }
        }
    }

    // ---- epilogue: normalize and store fp16 O
    float inv0 = 1.0f / l0, inv1 = 1.0f / l1;
    int r0 = q0 + warp * 16 + g;
    size_t ob0 = (rowbase + r0) * HH + hoff;
    size_t ob1 = ob0 + (size_t)8 * HH;
    #pragma unroll
    for (int nt = 0; nt < 16; nt++) {
        int col = nt * 8 + 2 * t;
        __half2 v0, v1;
        v0.x = __float2half_rn(oa[nt][0] * inv0);
        v0.y = __float2half_rn(oa[nt][1] * inv0);
        v1.x = __float2half_rn(oa[nt][2] * inv1);
        v1.y = __float2half_rn(oa[nt][3] * inv1);
        *(__half2*)(o + ob0 + col) = v0;
        *(__half2*)(o + ob1 + col) = v1;
    }
}

// ---------------- launch ----------------------------------------------------
extern "C" void kernel_launch(void* const* d_in, const int* in_sizes, int n_in,
                              void* d_out, int out_size)
{
    const float* x        = (const float*)d_in[0];
    const float* ln_w     = (const float*)d_in[1];
    const float* ln_b     = (const float*)d_in[2];
    const float* c_attn_w = (const float*)d_in[3];
    const float* c_attn_b = (const float*)d_in[4];
    const float* c_proj_w = (const float*)d_in[5];
    const float* c_proj_b = (const float*)d_in[6];
    float* out = (float*)d_out;

    void *p_xn, *p_qkv, *p_o, *p_wa, *p_wp;
    cudaGetSymbolAddress(&p_xn,  g_xn);
    cudaGetSymbolAddress(&p_qkv, g_qkv);
    cudaGetSymbolAddress(&p_o,   g_o);
    cudaGetSymbolAddress(&p_wa,  g_wa);
    cudaGetSymbolAddress(&p_wp,  g_wp);
    __half* xn  = (__half*)p_xn;
    float*  qkv = (float*)p_qkv;
    __half* ov  = (__half*)p_o;
    __half* wa  = (__half*)p_wa;
    __half* wp  = (__half*)p_wp;

    cudaFuncSetAttribute(gemm_f16<false>,
                         cudaFuncAttributeMaxDynamicSharedMemorySize, GEMM_SMEM);
    cudaFuncSetAttribute(gemm_f16<true>,
                         cudaFuncAttributeMaxDynamicSharedMemorySize, GEMM_SMEM);
    cudaFuncSetAttribute(flash_tc_kernel,
                         cudaFuncAttributeMaxDynamicSharedMemorySize, FLASH_SMEM);

    // 0. transpose + fp16-cast weights to [N][K]
    transpose_h_kernel<<<dim3(QKVN / 32, HH / 32), 256>>>(c_attn_w, wa, HH, QKVN);
    transpose_h_kernel<<<dim3(HH / 32, HH / 32), 256>>>(c_proj_w, wp, HH, HH);

    // 1. LayerNorm (fp16 out)
    ln_kernel<<<MROWS, 256>>>(x, ln_w, ln_b, xn);

    // 2. QKV projection: [8192,2048] @ [2048,6144] + bias   (fp16 HMMA)
    gemm_f16<false><<<dim3(QKVN / 128, MROWS / 256), 256, GEMM_SMEM>>>(
        xn, wa, c_attn_b, nullptr, qkv, MROWS, QKVN, HH);

    // 3. causal flash attention (tf32 tensor cores), writes fp16 O
    flash_tc_kernel<<<dim3(SS / BLKQ, BB * NHH), 256, FLASH_SMEM>>>(qkv, ov);

    // 4. output projection + bias + residual   (fp16 HMMA)
    gemm_f16<true><<<dim3(HH / 128, MROWS / 256), 256, GEMM_SMEM>>>(
        ov, wp, c_proj_b, x, out, MROWS, HH, HH);
}

// round 12
// speedup vs baseline: 2.8533x; 1.2710x over previous
#include <cuda_runtime.h>
#include <cuda_fp16.h>
#include <cstdint>

#define BB 4
#define SS 2048
#define HH 2048
#define NHH 16
#define HDD 128
#define MROWS (BB*SS)      /* 8192 */
#define QKVN (3*HH)        /* 6144 */

// ---------------- scratch (static device allocations are allowed) ----------
__device__ __half g_xn [(size_t)MROWS * HH];
__device__ __half g_qkv[(size_t)MROWS * QKVN];
__device__ __half g_o  [(size_t)MROWS * HH];
__device__ __half g_wa [(size_t)QKVN * HH];   // c_attn_w^T : [6144][2048] fp16
__device__ __half g_wp [(size_t)HH * HH];     // c_proj_w^T : [2048][2048] fp16

__device__ __forceinline__ uint32_t smem_u32(const void* p) {
    uint32_t a;
    asm("{ .reg .u64 t; cvta.to.shared.u64 t, %1; cvt.u32.u64 %0, t; }"
        : "=r"(a) : "l"(p));
    return a;
}

// ---------------- LayerNorm (writes fp16) -----------------------------------
__global__ void __launch_bounds__(256) ln_kernel(
    const float* __restrict__ x, const float* __restrict__ w,
    const float* __restrict__ b, __half* __restrict__ out)
{
    int row = blockIdx.x;
    const float* xr = x + (size_t)row * HH;
    float v[8];
    float s = 0.f, s2 = 0.f;
    #pragma unroll
    for (int i = 0; i < 8; i++) {
        v[i] = xr[threadIdx.x + i * 256];
        s  += v[i];
        s2 += v[i] * v[i];
    }
    __shared__ float red0[8], red1[8];
    #pragma unroll
    for (int off = 16; off; off >>= 1) {
        s  += __shfl_xor_sync(0xffffffffu, s,  off);
        s2 += __shfl_xor_sync(0xffffffffu, s2, off);
    }
    int warp = threadIdx.x >> 5, lane = threadIdx.x & 31;
    if (lane == 0) { red0[warp] = s; red1[warp] = s2; }
    __syncthreads();
    if (warp == 0) {
        s  = red0[lane & 7];
        s2 = red1[lane & 7];
        #pragma unroll
        for (int off = 4; off; off >>= 1) {
            s  += __shfl_xor_sync(0xffffffffu, s,  off);
            s2 += __shfl_xor_sync(0xffffffffu, s2, off);
        }
        if (lane == 0) { red0[0] = s; red1[0] = s2; }
    }
    __syncthreads();
    float mu  = red0[0] * (1.f / HH);
    float var = red1[0] * (1.f / HH) - mu * mu;
    float rs  = rsqrtf(var + 1e-5f);
    size_t base = (size_t)row * HH;
    #pragma unroll
    for (int i = 0; i < 8; i++) {
        int c = threadIdx.x + i * 256;
        out[base + c] = __float2half_rn((v[i] - mu) * rs * w[c] + b[c]);
    }
}

// ---------------- weight transpose + fp16 cast: in[K][N] -> out[N][K] -------
__global__ void __launch_bounds__(256) transpose_h_kernel(
    const float* __restrict__ in, __half* __restrict__ out, int K, int N)
{
    __shared__ float t[32][33];
    int n0 = blockIdx.x * 32, k0 = blockIdx.y * 32;
    int x = threadIdx.x & 31, y4 = (threadIdx.x >> 5) * 4;
    #pragma unroll
    for (int i = 0; i < 4; i++)
        t[y4 + i][x] = in[(size_t)(k0 + y4 + i) * N + n0 + x];
    __syncthreads();
    #pragma unroll
    for (int i = 0; i < 4; i++)
        out[(size_t)(n0 + y4 + i) * K + k0 + x] = __float2half_rn(t[x][y4 + i]);
}

// ---------------- fp16 GEMM: C[M,N] = A[M,K] @ W[N,K]^T + bias [+res] -------
// Block tile 256(M) x 128(N), k-stage 32, 3-stage cp.async, 8 warps 64x64.
#define GA_ST 20480                       /* 256 rows * 80B (40 halfs) */
#define GB_ST 10240                       /* 128 rows * 80B */
#define GB_BASE (3 * GA_ST)               /* 61440 */
#define GEMM_SMEM (3 * (GA_ST + GB_ST))   /* 92160 */
#define SROW 20                           /* smem row stride in 32-bit words */

template<bool RES, bool HOUT>
__global__ void __launch_bounds__(256, 1) gemm_f16(
    const __half* __restrict__ A, const __half* __restrict__ W,
    const float* __restrict__ bias, const float* __restrict__ res,
    void* __restrict__ Cv, int M, int N, int K)
{
    extern __shared__ char smem[];
    uint32_t sb = smem_u32(smem);

    int tid  = threadIdx.x;
    int warp = tid >> 5, lane = tid & 31;
    int g = lane >> 2, t = lane & 3;
    int wm = (warp >> 1) * 64;
    int wn = (warp & 1) * 64;
    int bm = blockIdx.y * 256;
    int bn = blockIdx.x * 128;

    float acc[4][8][4];
    #pragma unroll
    for (int mi = 0; mi < 4; mi++)
        #pragma unroll
        for (int ni = 0; ni < 8; ni++)
            #pragma unroll
            for (int c = 0; c < 4; c++) acc[mi][ni][c] = 0.f;

    const int KT = K >> 5;          // 64 stages of k=32

    auto fill = [&](int kt) {
        int kk = kt * 32;
        int s = kt % 3;
        #pragma unroll
        for (int p = 0; p < 4; p++) {              // A: 1024 x 16B chunks
            int idx = tid + p * 256;
            int r = idx >> 2, c = idx & 3;
            uint32_t d = sb + s * GA_ST + r * 80 + c * 16;
            const __half* src = A + (size_t)(bm + r) * K + kk + c * 8;
            asm volatile("cp.async.cg.shared.global [%0], [%1], 16;" :: "r"(d), "l"(src) : "memory");
        }
        #pragma unroll
        for (int p = 0; p < 2; p++) {              // B: 512 x 16B chunks
            int idx = tid + p * 256;
            int r = idx >> 2, c = idx & 3;
            uint32_t d = sb + GB_BASE + s * GB_ST + r * 80 + c * 16;
            const __half* src = W + (size_t)(bn + r) * K + kk + c * 8;
            asm volatile("cp.async.cg.shared.global [%0], [%1], 16;" :: "r"(d), "l"(src) : "memory");
        }
        asm volatile("cp.async.commit_group;" ::: "memory");
    };

    fill(0);
    fill(1);

    for (int kt = 0; kt < KT; kt++) {
        asm volatile("cp.async.wait_group 1;" ::: "memory");
        __syncthreads();                           // stage kt ready
        if (kt + 2 < KT) fill(kt + 2);

        int s = kt % 3;
        const uint32_t* Aw = (const uint32_t*)(smem + s * GA_ST);
        const uint32_t* Bw = (const uint32_t*)(smem + GB_BASE + s * GB_ST);

        #pragma unroll
        for (int ks = 0; ks < 2; ks++) {           // two k16 steps per stage
            int kw = ks * 8;                       // word offset within row
            uint32_t af[4][4], bf[8][2];
            #pragma unroll
            for (int mi = 0; mi < 4; mi++) {
                int r0 = (wm + mi * 16 + g) * SROW + kw;
                int r1 = r0 + 8 * SROW;
                af[mi][0] = Aw[r0 + t];
                af[mi][1] = Aw[r1 + t];
                af[mi][2] = Aw[r0 + t + 4];
                af[mi][3] = Aw[r1 + t + 4];
            }
            #pragma unroll
            for (int ni = 0; ni < 8; ni++) {
                int nb = (wn + ni * 8 + g) * SROW + kw;
                bf[ni][0] = Bw[nb + t];
                bf[ni][1] = Bw[nb + t + 4];
            }
            #pragma unroll
            for (int mi = 0; mi < 4; mi++)
                #pragma unroll
                for (int ni = 0; ni < 8; ni++)
                    asm volatile(
                        "mma.sync.aligned.m16n8k16.row.col.f32.f16.f16.f32 "
                        "{%0,%1,%2,%3},{%4,%5,%6,%7},{%8,%9},{%0,%1,%2,%3};"
                        : "+f"(acc[mi][ni][0]), "+f"(acc[mi][ni][1]),
                          "+f"(acc[mi][ni][2]), "+f"(acc[mi][ni][3])
                        : "r"(af[mi][0]), "r"(af[mi][1]), "r"(af[mi][2]), "r"(af[mi][3]),
                          "r"(bf[ni][0]), "r"(bf[ni][1]));
        }
    }

    // ---- epilogue
    #pragma unroll
    for (int mi = 0; mi < 4; mi++) {
        int r0 = bm + wm + mi * 16 + g;
        #pragma unroll
        for (int ni = 0; ni < 8; ni++) {
            int c0 = bn + wn + ni * 8 + 2 * t;
            #pragma unroll
            for (int half_ = 0; half_ < 2; half_++) {
                int row = r0 + half_ * 8;
                float vx = acc[mi][ni][half_ * 2 + 0] + bias[c0];
                float vy = acc[mi][ni][half_ * 2 + 1] + bias[c0 + 1];
                if (RES) {
                    float2 rr = *(const float2*)(res + (size_t)row * N + c0);
                    vx += rr.x; vy += rr.y;
                }
                if (HOUT) {
                    *(__half2*)((__half*)Cv + (size_t)row * N + c0) =
                        __floats2half2_rn(vx, vy);
                } else {
                    float2 v; v.x = vx; v.y = vy;
                    *(float2*)((float*)Cv + (size_t)row * N + c0) = v;
                }
            }
        }
    }
}

// ---------------- fp16 tensor-core flash attention --------------------------
// Q tile 128 rows (16/warp), K/V tiles 64, all fp16 in smem (stride 136 halfs).
// QK^T and PV via mma.m16n8k16; P converted C-frag->A-frag by pure packing.
// V B-frags via ldmatrix.x2.trans (stride 272B -> conflict-free).
#define BLKQ 128
#define BLKK 64
#define FH 136                              /* smem row stride in halfs */
#define FHW 68                              /* .. in 32-bit words */
#define QB_H  (BLKQ * FH)                   /* 17408 halfs = 34816 B */
#define KVB_H (BLKK * FH)                   /* 8704 halfs = 17408 B */
#define FLASH_SMEM ((QB_H + 4 * KVB_H) * 2) /* 104448 B */

__global__ void __launch_bounds__(256) flash_f16_kernel(
    const __half* __restrict__ qkv, __half* __restrict__ o)
{
    extern __shared__ __half smh[];
    __half* Qs = smh;                        // [128][FH]
    __half* KV = smh + QB_H;                 // 2 x (K[64][FH], V[64][FH])

    int tid  = threadIdx.x;
    int warp = tid >> 5, lane = tid & 31;
    int g = lane >> 2, t = lane & 3;
    int qt = 15 - (int)blockIdx.x;           // heavy tiles first
    int bh = blockIdx.y;
    int b = bh >> 4, h = bh & 15;
    int q0 = qt * BLKQ;
    size_t rowbase = (size_t)b * SS;
    size_t hoff = (size_t)h * 128;
    const float scale = 0.08838834764831845f;   // 1/sqrt(128)

    // ---- load Q tile (fp16, 2048 x 16B chunks)
    #pragma unroll
    for (int i = 0; i < 8; i++) {
        int idx = tid + i * 256;
        int r = idx >> 4, c8 = (idx & 15) * 8;
        uint32_t d = smem_u32(Qs + r * FH + c8);
        const __half* src = qkv + (rowbase + q0 + r) * QKVN + hoff + c8;
        asm volatile("cp.async.cg.shared.global [%0], [%1], 16;" :: "r"(d), "l"(src) : "memory");
    }
    asm volatile("cp.async.commit_group;" ::: "memory");

    auto issue_tile = [&](int kt) {
        int kb = kt * BLKK;
        __half* Kb = KV + (kt & 1) * 2 * KVB_H;
        __half* Vb = Kb + KVB_H;
        #pragma unroll
        for (int i = 0; i < 4; i++) {
            int idx = tid + i * 256;         // 1024 x 16B chunks per operand
            int r = idx >> 4, c8 = (idx & 15) * 8;
            const __half* gk = qkv + (rowbase + kb + r) * QKVN + hoff + 2048 + c8;
            const __half* gv = gk + 2048;
            uint32_t sk = smem_u32(Kb + r * FH + c8);
            uint32_t sv = smem_u32(Vb + r * FH + c8);
            asm volatile("cp.async.cg.shared.global [%0], [%1], 16;" :: "r"(sk), "l"(gk) : "memory");
            asm volatile("cp.async.cg.shared.global [%0], [%1], 16;" :: "r"(sv), "l"(gv) : "memory");
        }
        asm volatile("cp.async.commit_group;" ::: "memory");
    };

    float m0 = -1e30f, m1 = -1e30f, l0 = 0.f, l1 = 0.f;
    float oa[16][4];
    #pragma unroll
    for (int nt = 0; nt < 16; nt++)
        #pragma unroll
        for (int c = 0; c < 4; c++) oa[nt][c] = 0.f;

    const int NKT = (q0 + BLKQ) / BLKK;      // 2*qt + 2
    const int myrow0 = q0 + warp * 16;
    const uint32_t* Qw = (const uint32_t*)Qs;
    const int aq0 = (warp * 16 + g) * FHW;
    const int aq1 = aq0 + 8 * FHW;
    // ldmatrix per-lane base: row (lane&15) of V tile
    uint32_t lm_base_off = (uint32_t)((lane & 15) * FH) * 2;

    issue_tile(0);

    for (int kt = 0; kt < NKT; kt++) {
        int kb = kt * BLKK;
        asm volatile("cp.async.wait_group 0;" ::: "memory");
        __syncthreads();
        if (kt + 1 < NKT) issue_tile(kt + 1);

        bool active = (kb <= myrow0 + 15);   // warp-uniform
        __half* Kb = KV + (kt & 1) * 2 * KVB_H;
        __half* Vb = Kb + KVB_H;

        if (active) {
            const uint32_t* Kw = (const uint32_t*)Kb;
            uint32_t vbase = smem_u32(Vb) + lm_base_off;

            // ---- S = Q @ K^T   (64 k16 mmas/warp)
            float s[8][4];
            #pragma unroll
            for (int n = 0; n < 8; n++)
                #pragma unroll
                for (int c = 0; c < 4; c++) s[n][c] = 0.f;

            #pragma unroll
            for (int j = 0; j < 8; j++) {            // d chunks of 16
                int kw = j * 8;
                uint32_t a0 = Qw[aq0 + kw + t];
                uint32_t a1 = Qw[aq1 + kw + t];
                uint32_t a2 = Qw[aq0 + kw + t + 4];
                uint32_t a3 = Qw[aq1 + kw + t + 4];
                #pragma unroll
                for (int n = 0; n < 8; n++) {
                    int nb = (n * 8 + g) * FHW + kw;
                    uint32_t b0 = Kw[nb + t];
                    uint32_t b1 = Kw[nb + t + 4];
                    asm volatile(
                        "mma.sync.aligned.m16n8k16.row.col.f32.f16.f16.f32 "
                        "{%0,%1,%2,%3},{%4,%5,%6,%7},{%8,%9},{%0,%1,%2,%3};"
                        : "+f"(s[n][0]), "+f"(s[n][1]), "+f"(s[n][2]), "+f"(s[n][3])
                        : "r"(a0), "r"(a1), "r"(a2), "r"(a3), "r"(b0), "r"(b1));
                }
            }

            // ---- scale, then causal mask
            #pragma unroll
            for (int n = 0; n < 8; n++) {
                s[n][0] *= scale; s[n][1] *= scale;
                s[n][2] *= scale; s[n][3] *= scale;
            }
            if (kb + BLKK - 1 > myrow0) {
                int r0 = myrow0 + g, r1 = r0 + 8;
                #pragma unroll
                for (int n = 0; n < 8; n++) {
                    int c = kb + n * 8 + 2 * t;
                    if (c     > r0) s[n][0] = -1e30f;
                    if (c + 1 > r0) s[n][1] = -1e30f;
                    if (c     > r1) s[n][2] = -1e30f;
                    if (c + 1 > r1) s[n][3] = -1e30f;
                }
            }

            // ---- online softmax (rows g and g+8)
            float mx0 = -1e30f, mx1 = -1e30f;
            #pragma unroll
            for (int n = 0; n < 8; n++) {
                mx0 = fmaxf(mx0, fmaxf(s[n][0], s[n][1]));
                mx1 = fmaxf(mx1, fmaxf(s[n][2], s[n][3]));
            }
            mx0 = fmaxf(mx0, __shfl_xor_sync(0xffffffffu, mx0, 1));
            mx0 = fmaxf(mx0, __shfl_xor_sync(0xffffffffu, mx0, 2));
            mx1 = fmaxf(mx1, __shfl_xor_sync(0xffffffffu, mx1, 1));
            mx1 = fmaxf(mx1, __shfl_xor_sync(0xffffffffu, mx1, 2));
            float mn0 = fmaxf(m0, mx0), mn1 = fmaxf(m1, mx1);
            float al0 = __expf(m0 - mn0), al1 = __expf(m1 - mn1);
            float ls0 = 0.f, ls1 = 0.f;
            #pragma unroll
            for (int n = 0; n < 8; n++) {
                s[n][0] = __expf(s[n][0] - mn0);
                s[n][1] = __expf(s[n][1] - mn0);
                s[n][2] = __expf(s[n][2] - mn1);
                s[n][3] = __expf(s[n][3] - mn1);
                ls0 += s[n][0] + s[n][1];
                ls1 += s[n][2] + s[n][3];
            }
            ls0 += __shfl_xor_sync(0xffffffffu, ls0, 1);
            ls0 += __shfl_xor_sync(0xffffffffu, ls0, 2);
            ls1 += __shfl_xor_sync(0xffffffffu, ls1, 1);
            ls1 += __shfl_xor_sync(0xffffffffu, ls1, 2);
            l0 = l0 * al0 + ls0;  l1 = l1 * al1 + ls1;
            m0 = mn0;  m1 = mn1;
            #pragma unroll
            for (int nt = 0; nt < 16; nt++) {
                oa[nt][0] *= al0; oa[nt][1] *= al0;
                oa[nt][2] *= al1; oa[nt][3] *= al1;
            }

            // ---- O += P @ V   (P pack in regs; V via ldmatrix.x2.trans)
            #pragma unroll
            for (int j = 0; j < 4; j++) {            // seq chunks of 16
                __half2 pa0 = __floats2half2_rn(s[2*j    ][0], s[2*j    ][1]);
                __half2 pa1 = __floats2half2_rn(s[2*j    ][2], s[2*j    ][3]);
                __half2 pa2 = __floats2half2_rn(s[2*j + 1][0], s[2*j + 1][1]);
                __half2 pa3 = __floats2half2_rn(s[2*j + 1][2], s[2*j + 1][3]);
                uint32_t a0 = *(uint32_t*)&pa0;
                uint32_t a1 = *(uint32_t*)&pa1;
                uint32_t a2 = *(uint32_t*)&pa2;
                uint32_t a3 = *(uint32_t*)&pa3;
                uint32_t vrow = vbase + (uint32_t)(16 * j * FH) * 2;
                #pragma unroll
                for (int nt = 0; nt < 16; nt++) {
                    uint32_t b0, b1;
                    uint32_t addr = vrow + (uint32_t)(nt * 8) * 2;
                    asm volatile(
                        "ldmatrix.sync.aligned.m8n8.x2.trans.shared.b16 {%0, %1}, [%2];"
                        : "=r"(b0), "=r"(b1) : "r"(addr));
                    asm volatile(
                        "mma.sync.aligned.m16n8k16.row.col.f32.f16.f16.f32 "
                        "{%0,%1,%2,%3},{%4,%5,%6,%7},{%8,%9},{%0,%1,%2,%3};"
                        : "+f"(oa[nt][0]), "+f"(oa[nt][1]), "+f"(oa[nt][2]), "+f"(oa[nt][3])
                        : "r"(a0), "r"(a1), "r"(a2), "r"(a3), "r"(b0), "r"(b1));
                }
            }
        }
    }

    // ---- epilogue: normalize and store fp16 O
    float inv0 = 1.0f / l0, inv1 = 1.0f / l1;
    int r0 = q0 + warp * 16 + g;
    size_t ob0 = (rowbase + r0) * HH + hoff;
    size_t ob1 = ob0 + (size_t)8 * HH;
    #pragma unroll
    for (int nt = 0; nt < 16; nt++) {
        int col = nt * 8 + 2 * t;
        *(__half2*)(o + ob0 + col) = __floats2half2_rn(oa[nt][0] * inv0, oa[nt][1] * inv0);
        *(__half2*)(o + ob1 + col) = __floats2half2_rn(oa[nt][2] * inv1, oa[nt][3] * inv1);
    }
}

// ---------------- launch ----------------------------------------------------
extern "C" void kernel_launch(void* const* d_in, const int* in_sizes, int n_in,
                              void* d_out, int out_size)
{
    const float* x        = (const float*)d_in[0];
    const float* ln_w     = (const float*)d_in[1];
    const float* ln_b     = (const float*)d_in[2];
    const float* c_attn_w = (const float*)d_in[3];
    const float* c_attn_b = (const float*)d_in[4];
    const float* c_proj_w = (const float*)d_in[5];
    const float* c_proj_b = (const float*)d_in[6];
    float* out = (float*)d_out;

    void *p_xn, *p_qkv, *p_o, *p_wa, *p_wp;
    cudaGetSymbolAddress(&p_xn,  g_xn);
    cudaGetSymbolAddress(&p_qkv, g_qkv);
    cudaGetSymbolAddress(&p_o,   g_o);
    cudaGetSymbolAddress(&p_wa,  g_wa);
    cudaGetSymbolAddress(&p_wp,  g_wp);
    __half* xn  = (__half*)p_xn;
    __half* qkv = (__half*)p_qkv;
    __half* ov  = (__half*)p_o;
    __half* wa  = (__half*)p_wa;
    __half* wp  = (__half*)p_wp;

    cudaFuncSetAttribute((const void*)gemm_f16<false, true>,
                         cudaFuncAttributeMaxDynamicSharedMemorySize, GEMM_SMEM);
    cudaFuncSetAttribute((const void*)gemm_f16<true, false>,
                         cudaFuncAttributeMaxDynamicSharedMemorySize, GEMM_SMEM);
    cudaFuncSetAttribute((const void*)flash_f16_kernel,
                         cudaFuncAttributeMaxDynamicSharedMemorySize, FLASH_SMEM);

    // 0. transpose + fp16-cast weights to [N][K]
    transpose_h_kernel<<<dim3(QKVN / 32, HH / 32), 256>>>(c_attn_w, wa, HH, QKVN);
    transpose_h_kernel<<<dim3(HH / 32, HH / 32), 256>>>(c_proj_w, wp, HH, HH);

    // 1. LayerNorm (fp16 out)
    ln_kernel<<<MROWS, 256>>>(x, ln_w, ln_b, xn);

    // 2. QKV projection: [8192,2048] @ [2048,6144] + bias  -> fp16 qkv
    gemm_f16<false, true><<<dim3(QKVN / 128, MROWS / 256), 256, GEMM_SMEM>>>(
        xn, wa, c_attn_b, nullptr, qkv, MROWS, QKVN, HH);

    // 3. causal flash attention (fp16 tensor cores) -> fp16 O
    flash_f16_kernel<<<dim3(SS / BLKQ, BB * NHH), 256, FLASH_SMEM>>>(qkv, ov);

    // 4. output projection + bias + residual -> fp32 out
    gemm_f16<true, false><<<dim3(HH / 128, MROWS / 256), 256, GEMM_SMEM>>>(
        ov, wp, c_proj_b, x, out, MROWS, HH, HH);
}

// round 13
// speedup vs baseline: 2.9812x; 1.0448x over previous
#include <cuda_runtime.h>
#include <cuda_fp16.h>
#include <cstdint>

#define BB 4
#define SS 2048
#define HH 2048
#define NHH 16
#define HDD 128
#define MROWS (BB*SS)      /* 8192 */
#define QKVN (3*HH)        /* 6144 */

// ---------------- scratch (static device allocations are allowed) ----------
__device__ __half g_xn [(size_t)MROWS * HH];
__device__ __half g_qkv[(size_t)MROWS * QKVN];
__device__ __half g_o  [(size_t)MROWS * HH];
__device__ __half g_wa [(size_t)QKVN * HH];   // c_attn_w^T : [6144][2048] fp16
__device__ __half g_wp [(size_t)HH * HH];     // c_proj_w^T : [2048][2048] fp16

__device__ __forceinline__ uint32_t smem_u32(const void* p) {
    uint32_t a;
    asm("{ .reg .u64 t; cvta.to.shared.u64 t, %1; cvt.u32.u64 %0, t; }"
        : "=r"(a) : "l"(p));
    return a;
}

// ---------------- LayerNorm (writes fp16) -----------------------------------
__global__ void __launch_bounds__(256) ln_kernel(
    const float* __restrict__ x, const float* __restrict__ w,
    const float* __restrict__ b, __half* __restrict__ out)
{
    int row = blockIdx.x;
    const float* xr = x + (size_t)row * HH;
    float v[8];
    float s = 0.f, s2 = 0.f;
    #pragma unroll
    for (int i = 0; i < 8; i++) {
        v[i] = xr[threadIdx.x + i * 256];
        s  += v[i];
        s2 += v[i] * v[i];
    }
    __shared__ float red0[8], red1[8];
    #pragma unroll
    for (int off = 16; off; off >>= 1) {
        s  += __shfl_xor_sync(0xffffffffu, s,  off);
        s2 += __shfl_xor_sync(0xffffffffu, s2, off);
    }
    int warp = threadIdx.x >> 5, lane = threadIdx.x & 31;
    if (lane == 0) { red0[warp] = s; red1[warp] = s2; }
    __syncthreads();
    if (warp == 0) {
        s  = red0[lane & 7];
        s2 = red1[lane & 7];
        #pragma unroll
        for (int off = 4; off; off >>= 1) {
            s  += __shfl_xor_sync(0xffffffffu, s,  off);
            s2 += __shfl_xor_sync(0xffffffffu, s2, off);
        }
        if (lane == 0) { red0[0] = s; red1[0] = s2; }
    }
    __syncthreads();
    float mu  = red0[0] * (1.f / HH);
    float var = red1[0] * (1.f / HH) - mu * mu;
    float rs  = rsqrtf(var + 1e-5f);
    size_t base = (size_t)row * HH;
    #pragma unroll
    for (int i = 0; i < 8; i++) {
        int c = threadIdx.x + i * 256;
        out[base + c] = __float2half_rn((v[i] - mu) * rs * w[c] + b[c]);
    }
}

// ---------------- weight transpose + fp16 cast: in[K][N] -> out[N][K] -------
__global__ void __launch_bounds__(256) transpose_h_kernel(
    const float* __restrict__ in, __half* __restrict__ out, int K, int N)
{
    __shared__ float t[32][33];
    int n0 = blockIdx.x * 32, k0 = blockIdx.y * 32;
    int x = threadIdx.x & 31, y4 = (threadIdx.x >> 5) * 4;
    #pragma unroll
    for (int i = 0; i < 4; i++)
        t[y4 + i][x] = in[(size_t)(k0 + y4 + i) * N + n0 + x];
    __syncthreads();
    #pragma unroll
    for (int i = 0; i < 4; i++)
        out[(size_t)(n0 + y4 + i) * K + k0 + x] = __float2half_rn(t[x][y4 + i]);
}

// ---------------- fp16 GEMM: C[M,N] = A[M,K] @ W[N,K]^T + bias [+res] -------
// Block tile 128(M) x 128(N), k-stage 32, 3-stage cp.async.
// 8 warps of 64(M) x 32(N); __launch_bounds__(256,2) -> 2 CTAs/SM (16 warps)
// so barrier/wait gaps of one CTA overlap the other CTA's HMMA stream.
#define GA2_ST 10240                      /* 128 rows * 80B (40 halfs) */
#define GB2_ST 10240                      /* 128 rows * 80B */
#define GB2_BASE (3 * GA2_ST)             /* 30720 */
#define GEMM_SMEM (3 * (GA2_ST + GB2_ST)) /* 61440 */
#define SROW 20                           /* smem row stride in 32-bit words */

template<bool RES, bool HOUT>
__global__ void __launch_bounds__(256, 2) gemm_f16(
    const __half* __restrict__ A, const __half* __restrict__ W,
    const float* __restrict__ bias, const float* __restrict__ res,
    void* __restrict__ Cv, int M, int N, int K)
{
    extern __shared__ char smem[];
    uint32_t sb = smem_u32(smem);

    int tid  = threadIdx.x;
    int warp = tid >> 5, lane = tid & 31;
    int g = lane >> 2, t = lane & 3;
    int wm = (warp & 1) * 64;
    int wn = (warp >> 1) * 32;
    int bm = blockIdx.y * 128;
    int bn = blockIdx.x * 128;

    float acc[4][4][4];
    #pragma unroll
    for (int mi = 0; mi < 4; mi++)
        #pragma unroll
        for (int ni = 0; ni < 4; ni++)
            #pragma unroll
            for (int c = 0; c < 4; c++) acc[mi][ni][c] = 0.f;

    const int KT = K >> 5;          // 64 stages of k=32

    auto fill = [&](int kt) {
        int kk = kt * 32;
        int s = kt % 3;
        #pragma unroll
        for (int p = 0; p < 2; p++) {              // A: 512 x 16B chunks
            int idx = tid + p * 256;
            int r = idx >> 2, c = idx & 3;
            uint32_t d = sb + s * GA2_ST + r * 80 + c * 16;
            const __half* src = A + (size_t)(bm + r) * K + kk + c * 8;
            asm volatile("cp.async.cg.shared.global [%0], [%1], 16;" :: "r"(d), "l"(src) : "memory");
        }
        #pragma unroll
        for (int p = 0; p < 2; p++) {              // B: 512 x 16B chunks
            int idx = tid + p * 256;
            int r = idx >> 2, c = idx & 3;
            uint32_t d = sb + GB2_BASE + s * GB2_ST + r * 80 + c * 16;
            const __half* src = W + (size_t)(bn + r) * K + kk + c * 8;
            asm volatile("cp.async.cg.shared.global [%0], [%1], 16;" :: "r"(d), "l"(src) : "memory");
        }
        asm volatile("cp.async.commit_group;" ::: "memory");
    };

    fill(0);
    fill(1);

    for (int kt = 0; kt < KT; kt++) {
        asm volatile("cp.async.wait_group 1;" ::: "memory");
        __syncthreads();                           // stage kt ready
        if (kt + 2 < KT) fill(kt + 2);

        int s = kt % 3;
        const uint32_t* Aw = (const uint32_t*)(smem + s * GA2_ST);
        const uint32_t* Bw = (const uint32_t*)(smem + GB2_BASE + s * GB2_ST);

        #pragma unroll
        for (int ks = 0; ks < 2; ks++) {           // two k16 steps per stage
            int kw = ks * 8;                       // word offset within row
            uint32_t af[4][4], bf[4][2];
            #pragma unroll
            for (int mi = 0; mi < 4; mi++) {
                int r0 = (wm + mi * 16 + g) * SROW + kw;
                int r1 = r0 + 8 * SROW;
                af[mi][0] = Aw[r0 + t];
                af[mi][1] = Aw[r1 + t];
                af[mi][2] = Aw[r0 + t + 4];
                af[mi][3] = Aw[r1 + t + 4];
            }
            #pragma unroll
            for (int ni = 0; ni < 4; ni++) {
                int nb = (wn + ni * 8 + g) * SROW + kw;
                bf[ni][0] = Bw[nb + t];
                bf[ni][1] = Bw[nb + t + 4];
            }
            #pragma unroll
            for (int mi = 0; mi < 4; mi++)
                #pragma unroll
                for (int ni = 0; ni < 4; ni++)
                    asm volatile(
                        "mma.sync.aligned.m16n8k16.row.col.f32.f16.f16.f32 "
                        "{%0,%1,%2,%3},{%4,%5,%6,%7},{%8,%9},{%0,%1,%2,%3};"
                        : "+f"(acc[mi][ni][0]), "+f"(acc[mi][ni][1]),
                          "+f"(acc[mi][ni][2]), "+f"(acc[mi][ni][3])
                        : "r"(af[mi][0]), "r"(af[mi][1]), "r"(af[mi][2]), "r"(af[mi][3]),
                          "r"(bf[ni][0]), "r"(bf[ni][1]));
        }
    }

    // ---- epilogue
    #pragma unroll
    for (int mi = 0; mi < 4; mi++) {
        int r0 = bm + wm + mi * 16 + g;
        #pragma unroll
        for (int ni = 0; ni < 4; ni++) {
            int c0 = bn + wn + ni * 8 + 2 * t;
            #pragma unroll
            for (int half_ = 0; half_ < 2; half_++) {
                int row = r0 + half_ * 8;
                float vx = acc[mi][ni][half_ * 2 + 0] + bias[c0];
                float vy = acc[mi][ni][half_ * 2 + 1] + bias[c0 + 1];
                if (RES) {
                    float2 rr = *(const float2*)(res + (size_t)row * N + c0);
                    vx += rr.x; vy += rr.y;
                }
                if (HOUT) {
                    *(__half2*)((__half*)Cv + (size_t)row * N + c0) =
                        __floats2half2_rn(vx, vy);
                } else {
                    float2 v; v.x = vx; v.y = vy;
                    *(float2*)((float*)Cv + (size_t)row * N + c0) = v;
                }
            }
        }
    }
}

// ---------------- fp16 tensor-core flash attention --------------------------
#define BLKQ 128
#define BLKK 64
#define FH 136                              /* smem row stride in halfs */
#define FHW 68                              /* .. in 32-bit words */
#define QB_H  (BLKQ * FH)                   /* 17408 halfs = 34816 B */
#define KVB_H (BLKK * FH)                   /* 8704 halfs = 17408 B */
#define FLASH_SMEM ((QB_H + 4 * KVB_H) * 2) /* 104448 B */

__global__ void __launch_bounds__(256) flash_f16_kernel(
    const __half* __restrict__ qkv, __half* __restrict__ o)
{
    extern __shared__ __half smh[];
    __half* Qs = smh;                        // [128][FH]
    __half* KV = smh + QB_H;                 // 2 x (K[64][FH], V[64][FH])

    int tid  = threadIdx.x;
    int warp = tid >> 5, lane = tid & 31;
    int g = lane >> 2, t = lane & 3;
    int qt = 15 - (int)blockIdx.x;           // heavy tiles first
    int bh = blockIdx.y;
    int b = bh >> 4, h = bh & 15;
    int q0 = qt * BLKQ;
    size_t rowbase = (size_t)b * SS;
    size_t hoff = (size_t)h * 128;
    const float scale = 0.08838834764831845f;   // 1/sqrt(128)

    // ---- load Q tile (fp16, 2048 x 16B chunks)
    #pragma unroll
    for (int i = 0; i < 8; i++) {
        int idx = tid + i * 256;
        int r = idx >> 4, c8 = (idx & 15) * 8;
        uint32_t d = smem_u32(Qs + r * FH + c8);
        const __half* src = qkv + (rowbase + q0 + r) * QKVN + hoff + c8;
        asm volatile("cp.async.cg.shared.global [%0], [%1], 16;" :: "r"(d), "l"(src) : "memory");
    }
    asm volatile("cp.async.commit_group;" ::: "memory");

    auto issue_tile = [&](int kt) {
        int kb = kt * BLKK;
        __half* Kb = KV + (kt & 1) * 2 * KVB_H;
        __half* Vb = Kb + KVB_H;
        #pragma unroll
        for (int i = 0; i < 4; i++) {
            int idx = tid + i * 256;         // 1024 x 16B chunks per operand
            int r = idx >> 4, c8 = (idx & 15) * 8;
            const __half* gk = qkv + (rowbase + kb + r) * QKVN + hoff + 2048 + c8;
            const __half* gv = gk + 2048;
            uint32_t sk = smem_u32(Kb + r * FH + c8);
            uint32_t sv = smem_u32(Vb + r * FH + c8);
            asm volatile("cp.async.cg.shared.global [%0], [%1], 16;" :: "r"(sk), "l"(gk) : "memory");
            asm volatile("cp.async.cg.shared.global [%0], [%1], 16;" :: "r"(sv), "l"(gv) : "memory");
        }
        asm volatile("cp.async.commit_group;" ::: "memory");
    };

    float m0 = -1e30f, m1 = -1e30f, l0 = 0.f, l1 = 0.f;
    float oa[16][4];
    #pragma unroll
    for (int nt = 0; nt < 16; nt++)
        #pragma unroll
        for (int c = 0; c < 4; c++) oa[nt][c] = 0.f;

    const int NKT = (q0 + BLKQ) / BLKK;      // 2*qt + 2
    const int myrow0 = q0 + warp * 16;
    const uint32_t* Qw = (const uint32_t*)Qs;
    const int aq0 = (warp * 16 + g) * FHW;
    const int aq1 = aq0 + 8 * FHW;
    uint32_t lm_base_off = (uint32_t)((lane & 15) * FH) * 2;

    issue_tile(0);

    for (int kt = 0; kt < NKT; kt++) {
        int kb = kt * BLKK;
        asm volatile("cp.async.wait_group 0;" ::: "memory");
        __syncthreads();
        if (kt + 1 < NKT) issue_tile(kt + 1);

        bool active = (kb <= myrow0 + 15);   // warp-uniform
        __half* Kb = KV + (kt & 1) * 2 * KVB_H;
        __half* Vb = Kb + KVB_H;

        if (active) {
            const uint32_t* Kw = (const uint32_t*)Kb;
            uint32_t vbase = smem_u32(Vb) + lm_base_off;

            // ---- S = Q @ K^T   (64 k16 mmas/warp)
            float s[8][4];
            #pragma unroll
            for (int n = 0; n < 8; n++)
                #pragma unroll
                for (int c = 0; c < 4; c++) s[n][c] = 0.f;

            #pragma unroll
            for (int j = 0; j < 8; j++) {            // d chunks of 16
                int kw = j * 8;
                uint32_t a0 = Qw[aq0 + kw + t];
                uint32_t a1 = Qw[aq1 + kw + t];
                uint32_t a2 = Qw[aq0 + kw + t + 4];
                uint32_t a3 = Qw[aq1 + kw + t + 4];
                #pragma unroll
                for (int n = 0; n < 8; n++) {
                    int nb = (n * 8 + g) * FHW + kw;
                    uint32_t b0 = Kw[nb + t];
                    uint32_t b1 = Kw[nb + t + 4];
                    asm volatile(
                        "mma.sync.aligned.m16n8k16.row.col.f32.f16.f16.f32 "
                        "{%0,%1,%2,%3},{%4,%5,%6,%7},{%8,%9},{%0,%1,%2,%3};"
                        : "+f"(s[n][0]), "+f"(s[n][1]), "+f"(s[n][2]), "+f"(s[n][3])
                        : "r"(a0), "r"(a1), "r"(a2), "r"(a3), "r"(b0), "r"(b1));
                }
            }

            // ---- scale, then causal mask
            #pragma unroll
            for (int n = 0; n < 8; n++) {
                s[n][0] *= scale; s[n][1] *= scale;
                s[n][2] *= scale; s[n][3] *= scale;
            }
            if (kb + BLKK - 1 > myrow0) {
                int r0 = myrow0 + g, r1 = r0 + 8;
                #pragma unroll
                for (int n = 0; n < 8; n++) {
                    int c = kb + n * 8 + 2 * t;
                    if (c     > r0) s[n][0] = -1e30f;
                    if (c + 1 > r0) s[n][1] = -1e30f;
                    if (c     > r1) s[n][2] = -1e30f;
                    if (c + 1 > r1) s[n][3] = -1e30f;
                }
            }

            // ---- online softmax (rows g and g+8)
            float mx0 = -1e30f, mx1 = -1e30f;
            #pragma unroll
            for (int n = 0; n < 8; n++) {
                mx0 = fmaxf(mx0, fmaxf(s[n][0], s[n][1]));
                mx1 = fmaxf(mx1, fmaxf(s[n][2], s[n][3]));
            }
            mx0 = fmaxf(mx0, __shfl_xor_sync(0xffffffffu, mx0, 1));
            mx0 = fmaxf(mx0, __shfl_xor_sync(0xffffffffu, mx0, 2));
            mx1 = fmaxf(mx1, __shfl_xor_sync(0xffffffffu, mx1, 1));
            mx1 = fmaxf(mx1, __shfl_xor_sync(0xffffffffu, mx1, 2));
            float mn0 = fmaxf(m0, mx0), mn1 = fmaxf(m1, mx1);
            float al0 = __expf(m0 - mn0), al1 = __expf(m1 - mn1);
            float ls0 = 0.f, ls1 = 0.f;
            #pragma unroll
            for (int n = 0; n < 8; n++) {
                s[n][0] = __expf(s[n][0] - mn0);
                s[n][1] = __expf(s[n][1] - mn0);
                s[n][2] = __expf(s[n][2] - mn1);
                s[n][3] = __expf(s[n][3] - mn1);
                ls0 += s[n][0] + s[n][1];
                ls1 += s[n][2] + s[n][3];
            }
            ls0 += __shfl_xor_sync(0xffffffffu, ls0, 1);
            ls0 += __shfl_xor_sync(0xffffffffu, ls0, 2);
            ls1 += __shfl_xor_sync(0xffffffffu, ls1, 1);
            ls1 += __shfl_xor_sync(0xffffffffu, ls1, 2);
            l0 = l0 * al0 + ls0;  l1 = l1 * al1 + ls1;
            m0 = mn0;  m1 = mn1;
            #pragma unroll
            for (int nt = 0; nt < 16; nt++) {
                oa[nt][0] *= al0; oa[nt][1] *= al0;
                oa[nt][2] *= al1; oa[nt][3] *= al1;
            }

            // ---- O += P @ V   (P pack in regs; V via ldmatrix.x2.trans)
            #pragma unroll
            for (int j = 0; j < 4; j++) {            // seq chunks of 16
                __half2 pa0 = __floats2half2_rn(s[2*j    ][0], s[2*j    ][1]);
                __half2 pa1 = __floats2half2_rn(s[2*j    ][2], s[2*j    ][3]);
                __half2 pa2 = __floats2half2_rn(s[2*j + 1][0], s[2*j + 1][1]);
                __half2 pa3 = __floats2half2_rn(s[2*j + 1][2], s[2*j + 1][3]);
                uint32_t a0 = *(uint32_t*)&pa0;
                uint32_t a1 = *(uint32_t*)&pa1;
                uint32_t a2 = *(uint32_t*)&pa2;
                uint32_t a3 = *(uint32_t*)&pa3;
                uint32_t vrow = vbase + (uint32_t)(16 * j * FH) * 2;
                #pragma unroll
                for (int nt = 0; nt < 16; nt++) {
                    uint32_t b0, b1;
                    uint32_t addr = vrow + (uint32_t)(nt * 8) * 2;
                    asm volatile(
                        "ldmatrix.sync.aligned.m8n8.x2.trans.shared.b16 {%0, %1}, [%2];"
                        : "=r"(b0), "=r"(b1) : "r"(addr));
                    asm volatile(
                        "mma.sync.aligned.m16n8k16.row.col.f32.f16.f16.f32 "
                        "{%0,%1,%2,%3},{%4,%5,%6,%7},{%8,%9},{%0,%1,%2,%3};"
                        : "+f"(oa[nt][0]), "+f"(oa[nt][1]), "+f"(oa[nt][2]), "+f"(oa[nt][3])
                        : "r"(a0), "r"(a1), "r"(a2), "r"(a3), "r"(b0), "r"(b1));
                }
            }
        }
    }

    // ---- epilogue: normalize and store fp16 O
    float inv0 = 1.0f / l0, inv1 = 1.0f / l1;
    int r0 = q0 + warp * 16 + g;
    size_t ob0 = (rowbase + r0) * HH + hoff;
    size_t ob1 = ob0 + (size_t)8 * HH;
    #pragma unroll
    for (int nt = 0; nt < 16; nt++) {
        int col = nt * 8 + 2 * t;
        *(__half2*)(o + ob0 + col) = __floats2half2_rn(oa[nt][0] * inv0, oa[nt][1] * inv0);
        *(__half2*)(o + ob1 + col) = __floats2half2_rn(oa[nt][2] * inv1, oa[nt][3] * inv1);
    }
}

// ---------------- launch ----------------------------------------------------
extern "C" void kernel_launch(void* const* d_in, const int* in_sizes, int n_in,
                              void* d_out, int out_size)
{
    const float* x        = (const float*)d_in[0];
    const float* ln_w     = (const float*)d_in[1];
    const float* ln_b     = (const float*)d_in[2];
    const float* c_attn_w = (const float*)d_in[3];
    const float* c_attn_b = (const float*)d_in[4];
    const float* c_proj_w = (const float*)d_in[5];
    const float* c_proj_b = (const float*)d_in[6];
    float* out = (float*)d_out;

    void *p_xn, *p_qkv, *p_o, *p_wa, *p_wp;
    cudaGetSymbolAddress(&p_xn,  g_xn);
    cudaGetSymbolAddress(&p_qkv, g_qkv);
    cudaGetSymbolAddress(&p_o,   g_o);
    cudaGetSymbolAddress(&p_wa,  g_wa);
    cudaGetSymbolAddress(&p_wp,  g_wp);
    __half* xn  = (__half*)p_xn;
    __half* qkv = (__half*)p_qkv;
    __half* ov  = (__half*)p_o;
    __half* wa  = (__half*)p_wa;
    __half* wp  = (__half*)p_wp;

    cudaFuncSetAttribute((const void*)gemm_f16<false, true>,
                         cudaFuncAttributeMaxDynamicSharedMemorySize, GEMM_SMEM);
    cudaFuncSetAttribute((const void*)gemm_f16<true, false>,
                         cudaFuncAttributeMaxDynamicSharedMemorySize, GEMM_SMEM);
    cudaFuncSetAttribute((const void*)flash_f16_kernel,
                         cudaFuncAttributeMaxDynamicSharedMemorySize, FLASH_SMEM);

    // 0. transpose + fp16-cast weights to [N][K]
    transpose_h_kernel<<<dim3(QKVN / 32, HH / 32), 256>>>(c_attn_w, wa, HH, QKVN);
    transpose_h_kernel<<<dim3(HH / 32, HH / 32), 256>>>(c_proj_w, wp, HH, HH);

    // 1. LayerNorm (fp16 out)
    ln_kernel<<<MROWS, 256>>>(x, ln_w, ln_b, xn);

    // 2. QKV projection: [8192,2048] @ [2048,6144] + bias  -> fp16 qkv
    gemm_f16<false, true><<<dim3(QKVN / 128, MROWS / 128), 256, GEMM_SMEM>>>(
        xn, wa, c_attn_b, nullptr, qkv, MROWS, QKVN, HH);

    // 3. causal flash attention (fp16 tensor cores) -> fp16 O
    flash_f16_kernel<<<dim3(SS / BLKQ, BB * NHH), 256, FLASH_SMEM>>>(qkv, ov);

    // 4. output projection + bias + residual -> fp32 out
    gemm_f16<true, false><<<dim3(HH / 128, MROWS / 128), 256, GEMM_SMEM>>>(
        ov, wp, c_proj_b, x, out, MROWS, HH, HH);
}

// round 14
// speedup vs baseline: 3.3655x; 1.1289x over previous
#include <cuda_runtime.h>
#include <cuda_fp16.h>
#include <cstdint>

#define BB 4
#define SS 2048
#define HH 2048
#define NHH 16
#define HDD 128
#define MROWS (BB*SS)      /* 8192 */
#define QKVN (3*HH)        /* 6144 */

// ---------------- scratch (static device allocations are allowed) ----------
__device__ __half g_xn [(size_t)MROWS * HH];
__device__ __half g_qkv[(size_t)MROWS * QKVN];
__device__ __half g_o  [(size_t)MROWS * HH];
__device__ __half g_wa [(size_t)QKVN * HH];   // c_attn_w^T : [6144][2048] fp16
__device__ __half g_wp [(size_t)HH * HH];     // c_proj_w^T : [2048][2048] fp16

__device__ __forceinline__ uint32_t smem_u32(const void* p) {
    uint32_t a;
    asm("{ .reg .u64 t; cvta.to.shared.u64 t, %1; cvt.u32.u64 %0, t; }"
        : "=r"(a) : "l"(p));
    return a;
}

// ---------------- LayerNorm (float4 loads, writes fp16) ---------------------
__global__ void __launch_bounds__(256) ln_kernel(
    const float* __restrict__ x, const float* __restrict__ w,
    const float* __restrict__ b, __half* __restrict__ out)
{
    int row = blockIdx.x;
    const float4* xr = (const float4*)(x + (size_t)row * HH);
    float4 v[2];
    float s = 0.f, s2 = 0.f;
    #pragma unroll
    for (int i = 0; i < 2; i++) {
        v[i] = xr[threadIdx.x + i * 256];
        s  += v[i].x + v[i].y + v[i].z + v[i].w;
        s2 += v[i].x*v[i].x + v[i].y*v[i].y + v[i].z*v[i].z + v[i].w*v[i].w;
    }
    __shared__ float red0[8], red1[8];
    #pragma unroll
    for (int off = 16; off; off >>= 1) {
        s  += __shfl_xor_sync(0xffffffffu, s,  off);
        s2 += __shfl_xor_sync(0xffffffffu, s2, off);
    }
    int warp = threadIdx.x >> 5, lane = threadIdx.x & 31;
    if (lane == 0) { red0[warp] = s; red1[warp] = s2; }
    __syncthreads();
    if (warp == 0) {
        s  = red0[lane & 7];
        s2 = red1[lane & 7];
        #pragma unroll
        for (int off = 4; off; off >>= 1) {
            s  += __shfl_xor_sync(0xffffffffu, s,  off);
            s2 += __shfl_xor_sync(0xffffffffu, s2, off);
        }
        if (lane == 0) { red0[0] = s; red1[0] = s2; }
    }
    __syncthreads();
    float mu  = red0[0] * (1.f / HH);
    float var = red1[0] * (1.f / HH) - mu * mu;
    float rs  = rsqrtf(var + 1e-5f);
    size_t base = (size_t)row * HH;
    #pragma unroll
    for (int i = 0; i < 2; i++) {
        int c = (threadIdx.x + i * 256) * 4;
        float4 wv = *(const float4*)(w + c);
        float4 bv = *(const float4*)(b + c);
        __half2 h0 = __floats2half2_rn((v[i].x - mu) * rs * wv.x + bv.x,
                                       (v[i].y - mu) * rs * wv.y + bv.y);
        __half2 h1 = __floats2half2_rn((v[i].z - mu) * rs * wv.z + bv.z,
                                       (v[i].w - mu) * rs * wv.w + bv.w);
        *(__half2*)(out + base + c)     = h0;
        *(__half2*)(out + base + c + 2) = h1;
    }
}

// ---------------- weight transpose + fp16 cast: in[K][N] -> out[N][K] -------
__global__ void __launch_bounds__(256) transpose_h_kernel(
    const float* __restrict__ in, __half* __restrict__ out, int K, int N)
{
    __shared__ float t[32][33];
    int n0 = blockIdx.x * 32, k0 = blockIdx.y * 32;
    int x = threadIdx.x & 31, y4 = (threadIdx.x >> 5) * 4;
    #pragma unroll
    for (int i = 0; i < 4; i++)
        t[y4 + i][x] = in[(size_t)(k0 + y4 + i) * N + n0 + x];
    __syncthreads();
    #pragma unroll
    for (int i = 0; i < 4; i++)
        out[(size_t)(n0 + y4 + i) * K + k0 + x] = __float2half_rn(t[x][y4 + i]);
}

// ---------------- fp16 GEMM: C[M,N] = A[M,K] @ W[N,K]^T + bias [+res] -------
// Block tile 128(M) x 128(N), k-stage 32, 3-stage cp.async, 2 CTAs/SM.
// Fragment loads via ldmatrix.x4 (rows stride 80B -> conflict-free phases).
#define GA2_ST 10240                      /* 128 rows * 80B (40 halfs) */
#define GB2_ST 10240                      /* 128 rows * 80B */
#define GB2_BASE (3 * GA2_ST)             /* 30720 */
#define GEMM_SMEM (3 * (GA2_ST + GB2_ST)) /* 61440 */

template<bool RES, bool HOUT>
__global__ void __launch_bounds__(256, 2) gemm_f16(
    const __half* __restrict__ A, const __half* __restrict__ W,
    const float* __restrict__ bias, const float* __restrict__ res,
    void* __restrict__ Cv, int M, int N, int K)
{
    extern __shared__ char smem[];
    uint32_t sb = smem_u32(smem);

    int tid  = threadIdx.x;
    int warp = tid >> 5, lane = tid & 31;
    int g = lane >> 2, t = lane & 3;
    int wm = (warp & 1) * 64;
    int wn = (warp >> 1) * 32;
    int bm = blockIdx.y * 128;
    int bn = blockIdx.x * 128;

    float acc[4][4][4];
    #pragma unroll
    for (int mi = 0; mi < 4; mi++)
        #pragma unroll
        for (int ni = 0; ni < 4; ni++)
            #pragma unroll
            for (int c = 0; c < 4; c++) acc[mi][ni][c] = 0.f;

    const int KT = K >> 5;          // 64 stages of k=32

    auto fill = [&](int kt) {
        int kk = kt * 32;
        int s = kt % 3;
        #pragma unroll
        for (int p = 0; p < 2; p++) {              // A: 512 x 16B chunks
            int idx = tid + p * 256;
            int r = idx >> 2, c = idx & 3;
            uint32_t d = sb + s * GA2_ST + r * 80 + c * 16;
            const __half* src = A + (size_t)(bm + r) * K + kk + c * 8;
            asm volatile("cp.async.cg.shared.global [%0], [%1], 16;" :: "r"(d), "l"(src) : "memory");
        }
        #pragma unroll
        for (int p = 0; p < 2; p++) {              // B: 512 x 16B chunks
            int idx = tid + p * 256;
            int r = idx >> 2, c = idx & 3;
            uint32_t d = sb + GB2_BASE + s * GB2_ST + r * 80 + c * 16;
            const __half* src = W + (size_t)(bn + r) * K + kk + c * 8;
            asm volatile("cp.async.cg.shared.global [%0], [%1], 16;" :: "r"(d), "l"(src) : "memory");
        }
        asm volatile("cp.async.commit_group;" ::: "memory");
    };

    fill(0);
    fill(1);

    // ldmatrix lane-address components (constant across stages)
    uint32_t a_lane = (uint32_t)((lane & 15) * 80 + (lane >> 4) * 16);
    uint32_t b_lane = (uint32_t)(((lane & 7) + ((lane >> 4) << 3)) * 80 + ((lane >> 3) & 1) * 16);

    for (int kt = 0; kt < KT; kt++) {
        asm volatile("cp.async.wait_group 1;" ::: "memory");
        __syncthreads();                           // stage kt ready
        if (kt + 2 < KT) fill(kt + 2);

        int s = kt % 3;
        uint32_t Ab = sb + s * GA2_ST;
        uint32_t Bb = sb + GB2_BASE + s * GB2_ST;

        #pragma unroll
        for (int ks = 0; ks < 2; ks++) {           // two k16 steps per stage
            uint32_t af[4][4], bf[4][2];
            uint32_t abase = Ab + a_lane + ks * 32 + (uint32_t)(wm * 80);
            #pragma unroll
            for (int mi = 0; mi < 4; mi++) {
                uint32_t addr = abase + mi * (16 * 80);
                asm volatile(
                    "ldmatrix.sync.aligned.m8n8.x4.shared.b16 {%0,%1,%2,%3}, [%4];"
                    : "=r"(af[mi][0]), "=r"(af[mi][1]), "=r"(af[mi][2]), "=r"(af[mi][3])
                    : "r"(addr));
            }
            uint32_t bbase = Bb + b_lane + ks * 32 + (uint32_t)(wn * 80);
            #pragma unroll
            for (int np = 0; np < 2; np++) {
                uint32_t addr = bbase + np * (16 * 80);
                asm volatile(
                    "ldmatrix.sync.aligned.m8n8.x4.shared.b16 {%0,%1,%2,%3}, [%4];"
                    : "=r"(bf[2*np][0]), "=r"(bf[2*np][1]),
                      "=r"(bf[2*np+1][0]), "=r"(bf[2*np+1][1])
                    : "r"(addr));
            }
            #pragma unroll
            for (int mi = 0; mi < 4; mi++)
                #pragma unroll
                for (int ni = 0; ni < 4; ni++)
                    asm volatile(
                        "mma.sync.aligned.m16n8k16.row.col.f32.f16.f16.f32 "
                        "{%0,%1,%2,%3},{%4,%5,%6,%7},{%8,%9},{%0,%1,%2,%3};"
                        : "+f"(acc[mi][ni][0]), "+f"(acc[mi][ni][1]),
                          "+f"(acc[mi][ni][2]), "+f"(acc[mi][ni][3])
                        : "r"(af[mi][0]), "r"(af[mi][1]), "r"(af[mi][2]), "r"(af[mi][3]),
                          "r"(bf[ni][0]), "r"(bf[ni][1]));
        }
    }

    // ---- epilogue
    #pragma unroll
    for (int mi = 0; mi < 4; mi++) {
        int r0 = bm + wm + mi * 16 + g;
        #pragma unroll
        for (int ni = 0; ni < 4; ni++) {
            int c0 = bn + wn + ni * 8 + 2 * t;
            #pragma unroll
            for (int half_ = 0; half_ < 2; half_++) {
                int row = r0 + half_ * 8;
                float vx = acc[mi][ni][half_ * 2 + 0] + bias[c0];
                float vy = acc[mi][ni][half_ * 2 + 1] + bias[c0 + 1];
                if (RES) {
                    float2 rr = *(const float2*)(res + (size_t)row * N + c0);
                    vx += rr.x; vy += rr.y;
                }
                if (HOUT) {
                    *(__half2*)((__half*)Cv + (size_t)row * N + c0) =
                        __floats2half2_rn(vx, vy);
                } else {
                    float2 v; v.x = vx; v.y = vy;
                    *(float2*)((float*)Cv + (size_t)row * N + c0) = v;
                }
            }
        }
    }
}

// ---------------- fp16 tensor-core flash attention --------------------------
#define BLKQ 128
#define BLKK 64
#define FH 136                              /* smem row stride in halfs */
#define QB_H  (BLKQ * FH)                   /* 17408 halfs = 34816 B */
#define KVB_H (BLKK * FH)                   /* 8704 halfs = 17408 B */
#define FLASH_SMEM ((QB_H + 4 * KVB_H) * 2) /* 104448 B */

__global__ void __launch_bounds__(256) flash_f16_kernel(
    const __half* __restrict__ qkv, __half* __restrict__ o)
{
    extern __shared__ __half smh[];
    __half* Qs = smh;                        // [128][FH]
    __half* KV = smh + QB_H;                 // 2 x (K[64][FH], V[64][FH])

    int tid  = threadIdx.x;
    int warp = tid >> 5, lane = tid & 31;
    int g = lane >> 2, t = lane & 3;
    int qt = 15 - (int)blockIdx.x;           // heavy tiles first
    int bh = blockIdx.y;
    int b = bh >> 4, h = bh & 15;
    int q0 = qt * BLKQ;
    size_t rowbase = (size_t)b * SS;
    size_t hoff = (size_t)h * 128;
    const float scale = 0.08838834764831845f;   // 1/sqrt(128)

    // ---- load Q tile (fp16, 2048 x 16B chunks)
    #pragma unroll
    for (int i = 0; i < 8; i++) {
        int idx = tid + i * 256;
        int r = idx >> 4, c8 = (idx & 15) * 8;
        uint32_t d = smem_u32(Qs + r * FH + c8);
        const __half* src = qkv + (rowbase + q0 + r) * QKVN + hoff + c8;
        asm volatile("cp.async.cg.shared.global [%0], [%1], 16;" :: "r"(d), "l"(src) : "memory");
    }
    asm volatile("cp.async.commit_group;" ::: "memory");

    auto issue_tile = [&](int kt) {
        int kb = kt * BLKK;
        __half* Kb = KV + (kt & 1) * 2 * KVB_H;
        __half* Vb = Kb + KVB_H;
        #pragma unroll
        for (int i = 0; i < 4; i++) {
            int idx = tid + i * 256;         // 1024 x 16B chunks per operand
            int r = idx >> 4, c8 = (idx & 15) * 8;
            const __half* gk = qkv + (rowbase + kb + r) * QKVN + hoff + 2048 + c8;
            const __half* gv = gk + 2048;
            uint32_t sk = smem_u32(Kb + r * FH + c8);
            uint32_t sv = smem_u32(Vb + r * FH + c8);
            asm volatile("cp.async.cg.shared.global [%0], [%1], 16;" :: "r"(sk), "l"(gk) : "memory");
            asm volatile("cp.async.cg.shared.global [%0], [%1], 16;" :: "r"(sv), "l"(gv) : "memory");
        }
        asm volatile("cp.async.commit_group;" ::: "memory");
    };

    float m0 = -1e30f, m1 = -1e30f, l0 = 0.f, l1 = 0.f;
    float oa[16][4];
    #pragma unroll
    for (int nt = 0; nt < 16; nt++)
        #pragma unroll
        for (int c = 0; c < 4; c++) oa[nt][c] = 0.f;

    const int NKT = (q0 + BLKQ) / BLKK;      // 2*qt + 2
    const int myrow0 = q0 + warp * 16;
    // ldmatrix lane addresses (stride 272B rows -> conflict-free phases)
    uint32_t q_lm = smem_u32(Qs) +
        (uint32_t)((warp * 16 + (lane & 15)) * FH) * 2 + (uint32_t)((lane >> 4) * 16);
    uint32_t k_lane = (uint32_t)(((lane & 7) + ((lane >> 4) << 3)) * FH) * 2 +
                      (uint32_t)(((lane >> 3) & 1) * 16);
    uint32_t lm_base_off = (uint32_t)((lane & 15) * FH) * 2;

    issue_tile(0);

    for (int kt = 0; kt < NKT; kt++) {
        int kb = kt * BLKK;
        asm volatile("cp.async.wait_group 0;" ::: "memory");
        __syncthreads();
        if (kt + 1 < NKT) issue_tile(kt + 1);

        bool active = (kb <= myrow0 + 15);   // warp-uniform
        __half* Kb = KV + (kt & 1) * 2 * KVB_H;
        __half* Vb = Kb + KVB_H;

        if (active) {
            uint32_t kbase = smem_u32(Kb) + k_lane;
            uint32_t vbase = smem_u32(Vb) + lm_base_off;

            // ---- S = Q @ K^T   (64 k16 mmas/warp, ldmatrix-fed)
            float s[8][4];
            #pragma unroll
            for (int n = 0; n < 8; n++)
                #pragma unroll
                for (int c = 0; c < 4; c++) s[n][c] = 0.f;

            #pragma unroll
            for (int j = 0; j < 8; j++) {            // d chunks of 16
                uint32_t a0, a1, a2, a3;
                asm volatile(
                    "ldmatrix.sync.aligned.m8n8.x4.shared.b16 {%0,%1,%2,%3}, [%4];"
                    : "=r"(a0), "=r"(a1), "=r"(a2), "=r"(a3)
                    : "r"(q_lm + j * 32));
                uint32_t bf[8][2];
                #pragma unroll
                for (int np = 0; np < 4; np++) {
                    uint32_t addr = kbase + np * (16 * FH * 2) + j * 32;
                    asm volatile(
                        "ldmatrix.sync.aligned.m8n8.x4.shared.b16 {%0,%1,%2,%3}, [%4];"
                        : "=r"(bf[2*np][0]), "=r"(bf[2*np][1]),
                          "=r"(bf[2*np+1][0]), "=r"(bf[2*np+1][1])
                        : "r"(addr));
                }
                #pragma unroll
                for (int n = 0; n < 8; n++)
                    asm volatile(
                        "mma.sync.aligned.m16n8k16.row.col.f32.f16.f16.f32 "
                        "{%0,%1,%2,%3},{%4,%5,%6,%7},{%8,%9},{%0,%1,%2,%3};"
                        : "+f"(s[n][0]), "+f"(s[n][1]), "+f"(s[n][2]), "+f"(s[n][3])
                        : "r"(a0), "r"(a1), "r"(a2), "r"(a3),
                          "r"(bf[n][0]), "r"(bf[n][1]));
            }

            // ---- scale, then causal mask
            #pragma unroll
            for (int n = 0; n < 8; n++) {
                s[n][0] *= scale; s[n][1] *= scale;
                s[n][2] *= scale; s[n][3] *= scale;
            }
            if (kb + BLKK - 1 > myrow0) {
                int r0 = myrow0 + g, r1 = r0 + 8;
                #pragma unroll
                for (int n = 0; n < 8; n++) {
                    int c = kb + n * 8 + 2 * t;
                    if (c     > r0) s[n][0] = -1e30f;
                    if (c + 1 > r0) s[n][1] = -1e30f;
                    if (c     > r1) s[n][2] = -1e30f;
                    if (c + 1 > r1) s[n][3] = -1e30f;
                }
            }

            // ---- online softmax (rows g and g+8)
            float mx0 = -1e30f, mx1 = -1e30f;
            #pragma unroll
            for (int n = 0; n < 8; n++) {
                mx0 = fmaxf(mx0, fmaxf(s[n][0], s[n][1]));
                mx1 = fmaxf(mx1, fmaxf(s[n][2], s[n][3]));
            }
            mx0 = fmaxf(mx0, __shfl_xor_sync(0xffffffffu, mx0, 1));
            mx0 = fmaxf(mx0, __shfl_xor_sync(0xffffffffu, mx0, 2));
            mx1 = fmaxf(mx1, __shfl_xor_sync(0xffffffffu, mx1, 1));
            mx1 = fmaxf(mx1, __shfl_xor_sync(0xffffffffu, mx1, 2));
            float mn0 = fmaxf(m0, mx0), mn1 = fmaxf(m1, mx1);
            float al0 = __expf(m0 - mn0), al1 = __expf(m1 - mn1);
            float ls0 = 0.f, ls1 = 0.f;
            #pragma unroll
            for (int n = 0; n < 8; n++) {
                s[n][0] = __expf(s[n][0] - mn0);
                s[n][1] = __expf(s[n][1] - mn0);
                s[n][2] = __expf(s[n][2] - mn1);
                s[n][3] = __expf(s[n][3] - mn1);
                ls0 += s[n][0] + s[n][1];
                ls1 += s[n][2] + s[n][3];
            }
            ls0 += __shfl_xor_sync(0xffffffffu, ls0, 1);
            ls0 += __shfl_xor_sync(0xffffffffu, ls0, 2);
            ls1 += __shfl_xor_sync(0xffffffffu, ls1, 1);
            ls1 += __shfl_xor_sync(0xffffffffu, ls1, 2);
            l0 = l0 * al0 + ls0;  l1 = l1 * al1 + ls1;
            m0 = mn0;  m1 = mn1;
            #pragma unroll
            for (int nt = 0; nt < 16; nt++) {
                oa[nt][0] *= al0; oa[nt][1] *= al0;
                oa[nt][2] *= al1; oa[nt][3] *= al1;
            }

            // ---- O += P @ V   (P pack in regs; V via ldmatrix.x2.trans)
            #pragma unroll
            for (int j = 0; j < 4; j++) {            // seq chunks of 16
                __half2 pa0 = __floats2half2_rn(s[2*j    ][0], s[2*j    ][1]);
                __half2 pa1 = __floats2half2_rn(s[2*j    ][2], s[2*j    ][3]);
                __half2 pa2 = __floats2half2_rn(s[2*j + 1][0], s[2*j + 1][1]);
                __half2 pa3 = __floats2half2_rn(s[2*j + 1][2], s[2*j + 1][3]);
                uint32_t a0 = *(uint32_t*)&pa0;
                uint32_t a1 = *(uint32_t*)&pa1;
                uint32_t a2 = *(uint32_t*)&pa2;
                uint32_t a3 = *(uint32_t*)&pa3;
                uint32_t vrow = vbase + (uint32_t)(16 * j * FH) * 2;
                #pragma unroll
                for (int nt = 0; nt < 16; nt++) {
                    uint32_t b0, b1;
                    uint32_t addr = vrow + (uint32_t)(nt * 8) * 2;
                    asm volatile(
                        "ldmatrix.sync.aligned.m8n8.x2.trans.shared.b16 {%0, %1}, [%2];"
                        : "=r"(b0), "=r"(b1) : "r"(addr));
                    asm volatile(
                        "mma.sync.aligned.m16n8k16.row.col.f32.f16.f16.f32 "
                        "{%0,%1,%2,%3},{%4,%5,%6,%7},{%8,%9},{%0,%1,%2,%3};"
                        : "+f"(oa[nt][0]), "+f"(oa[nt][1]), "+f"(oa[nt][2]), "+f"(oa[nt][3])
                        : "r"(a0), "r"(a1), "r"(a2), "r"(a3), "r"(b0), "r"(b1));
                }
            }
        }
    }

    // ---- epilogue: normalize and store fp16 O
    float inv0 = 1.0f / l0, inv1 = 1.0f / l1;
    int r0 = q0 + warp * 16 + g;
    size_t ob0 = (rowbase + r0) * HH + hoff;
    size_t ob1 = ob0 + (size_t)8 * HH;
    #pragma unroll
    for (int nt = 0; nt < 16; nt++) {
        int col = nt * 8 + 2 * t;
        *(__half2*)(o + ob0 + col) = __floats2half2_rn(oa[nt][0] * inv0, oa[nt][1] * inv0);
        *(__half2*)(o + ob1 + col) = __floats2half2_rn(oa[nt][2] * inv1, oa[nt][3] * inv1);
    }
}

// ---------------- launch ----------------------------------------------------
extern "C" void kernel_launch(void* const* d_in, const int* in_sizes, int n_in,
                              void* d_out, int out_size)
{
    const float* x        = (const float*)d_in[0];
    const float* ln_w     = (const float*)d_in[1];
    const float* ln_b     = (const float*)d_in[2];
    const float* c_attn_w = (const float*)d_in[3];
    const float* c_attn_b = (const float*)d_in[4];
    const float* c_proj_w = (const float*)d_in[5];
    const float* c_proj_b = (const float*)d_in[6];
    float* out = (float*)d_out;

    void *p_xn, *p_qkv, *p_o, *p_wa, *p_wp;
    cudaGetSymbolAddress(&p_xn,  g_xn);
    cudaGetSymbolAddress(&p_qkv, g_qkv);
    cudaGetSymbolAddress(&p_o,   g_o);
    cudaGetSymbolAddress(&p_wa,  g_wa);
    cudaGetSymbolAddress(&p_wp,  g_wp);
    __half* xn  = (__half*)p_xn;
    __half* qkv = (__half*)p_qkv;
    __half* ov  = (__half*)p_o;
    __half* wa  = (__half*)p_wa;
    __half* wp  = (__half*)p_wp;

    cudaFuncSetAttribute((const void*)gemm_f16<false, true>,
                         cudaFuncAttributeMaxDynamicSharedMemorySize, GEMM_SMEM);
    cudaFuncSetAttribute((const void*)gemm_f16<true, false>,
                         cudaFuncAttributeMaxDynamicSharedMemorySize, GEMM_SMEM);
    cudaFuncSetAttribute((const void*)flash_f16_kernel,
                         cudaFuncAttributeMaxDynamicSharedMemorySize, FLASH_SMEM);

    // 0. transpose + fp16-cast weights to [N][K]
    transpose_h_kernel<<<dim3(QKVN / 32, HH / 32), 256>>>(c_attn_w, wa, HH, QKVN);
    transpose_h_kernel<<<dim3(HH / 32, HH / 32), 256>>>(c_proj_w, wp, HH, HH);

    // 1. LayerNorm (fp16 out)
    ln_kernel<<<MROWS, 256>>>(x, ln_w, ln_b, xn);

    // 2. QKV projection: [8192,2048] @ [2048,6144] + bias  -> fp16 qkv
    gemm_f16<false, true><<<dim3(QKVN / 128, MROWS / 128), 256, GEMM_SMEM>>>(
        xn, wa, c_attn_b, nullptr, qkv, MROWS, QKVN, HH);

    // 3. causal flash attention (fp16 tensor cores) -> fp16 O
    flash_f16_kernel<<<dim3(SS / BLKQ, BB * NHH), 256, FLASH_SMEM>>>(qkv, ov);

    // 4. output projection + bias + residual -> fp32 out
    gemm_f16<true, false><<<dim3(HH / 128, MROWS / 128), 256, GEMM_SMEM>>>(
        ov, wp, c_proj_b, x, out, MROWS, HH, HH);
}

// round 15
// speedup vs baseline: 3.6474x; 1.0838x over previous
#include <cuda_runtime.h>
#include <cuda_fp16.h>
#include <cstdint>

#define BB 4
#define SS 2048
#define HH 2048
#define NHH 16
#define HDD 128
#define MROWS (BB*SS)      /* 8192 */
#define QKVN (3*HH)        /* 6144 */

// ---------------- scratch (static device allocations are allowed) ----------
__device__ __half g_xn [(size_t)MROWS * HH];
__device__ __half g_qkv[(size_t)MROWS * QKVN];
__device__ __half g_o  [(size_t)MROWS * HH];
__device__ __half g_wa [(size_t)QKVN * HH];   // c_attn_w^T : [6144][2048] fp16
__device__ __half g_wp [(size_t)HH * HH];     // c_proj_w^T : [2048][2048] fp16

__device__ __forceinline__ uint32_t smem_u32(const void* p) {
    uint32_t a;
    asm("{ .reg .u64 t; cvta.to.shared.u64 t, %1; cvt.u32.u64 %0, t; }"
        : "=r"(a) : "l"(p));
    return a;
}

// ---------------- LayerNorm (float4 loads, writes fp16) ---------------------
__global__ void __launch_bounds__(256) ln_kernel(
    const float* __restrict__ x, const float* __restrict__ w,
    const float* __restrict__ b, __half* __restrict__ out)
{
    int row = blockIdx.x;
    const float4* xr = (const float4*)(x + (size_t)row * HH);
    float4 v[2];
    float s = 0.f, s2 = 0.f;
    #pragma unroll
    for (int i = 0; i < 2; i++) {
        v[i] = xr[threadIdx.x + i * 256];
        s  += v[i].x + v[i].y + v[i].z + v[i].w;
        s2 += v[i].x*v[i].x + v[i].y*v[i].y + v[i].z*v[i].z + v[i].w*v[i].w;
    }
    __shared__ float red0[8], red1[8];
    #pragma unroll
    for (int off = 16; off; off >>= 1) {
        s  += __shfl_xor_sync(0xffffffffu, s,  off);
        s2 += __shfl_xor_sync(0xffffffffu, s2, off);
    }
    int warp = threadIdx.x >> 5, lane = threadIdx.x & 31;
    if (lane == 0) { red0[warp] = s; red1[warp] = s2; }
    __syncthreads();
    if (warp == 0) {
        s  = red0[lane & 7];
        s2 = red1[lane & 7];
        #pragma unroll
        for (int off = 4; off; off >>= 1) {
            s  += __shfl_xor_sync(0xffffffffu, s,  off);
            s2 += __shfl_xor_sync(0xffffffffu, s2, off);
        }
        if (lane == 0) { red0[0] = s; red1[0] = s2; }
    }
    __syncthreads();
    float mu  = red0[0] * (1.f / HH);
    float var = red1[0] * (1.f / HH) - mu * mu;
    float rs  = rsqrtf(var + 1e-5f);
    size_t base = (size_t)row * HH;
    #pragma unroll
    for (int i = 0; i < 2; i++) {
        int c = (threadIdx.x + i * 256) * 4;
        float4 wv = *(const float4*)(w + c);
        float4 bv = *(const float4*)(b + c);
        __half2 h0 = __floats2half2_rn((v[i].x - mu) * rs * wv.x + bv.x,
                                       (v[i].y - mu) * rs * wv.y + bv.y);
        __half2 h1 = __floats2half2_rn((v[i].z - mu) * rs * wv.z + bv.z,
                                       (v[i].w - mu) * rs * wv.w + bv.w);
        *(__half2*)(out + base + c)     = h0;
        *(__half2*)(out + base + c + 2) = h1;
    }
}

// ---------------- weight transpose + fp16 cast: in[K][N] -> out[N][K] -------
__global__ void __launch_bounds__(256) transpose_h_kernel(
    const float* __restrict__ in, __half* __restrict__ out, int K, int N)
{
    __shared__ float t[32][33];
    int n0 = blockIdx.x * 32, k0 = blockIdx.y * 32;
    int x = threadIdx.x & 31, y4 = (threadIdx.x >> 5) * 4;
    #pragma unroll
    for (int i = 0; i < 4; i++)
        t[y4 + i][x] = in[(size_t)(k0 + y4 + i) * N + n0 + x];
    __syncthreads();
    #pragma unroll
    for (int i = 0; i < 4; i++)
        out[(size_t)(n0 + y4 + i) * K + k0 + x] = __float2half_rn(t[x][y4 + i]);
}

// ---------------- fp16 GEMM: C[M,N] = A[M,K] @ W[N,K]^T + bias [+res] -------
// Block tile 128(M) x 128(N), 128 threads (4 warps of 64x64), k-stage 32,
// 3-stage cp.async, 2 CTAs/SM. ldmatrix.x4 fragment feeds:
// per k16 step 8 LDSM feed 32 HMMAs (4.0 mma/LDSM vs 2.67 before).
#define GA2_ST 10240                      /* 128 rows * 80B (40 halfs) */
#define GB2_ST 10240                      /* 128 rows * 80B */
#define GB2_BASE (3 * GA2_ST)             /* 30720 */
#define GEMM_SMEM (3 * (GA2_ST + GB2_ST)) /* 61440 */

template<bool RES, bool HOUT>
__global__ void __launch_bounds__(128, 2) gemm_f16(
    const __half* __restrict__ A, const __half* __restrict__ W,
    const float* __restrict__ bias, const float* __restrict__ res,
    void* __restrict__ Cv, int M, int N, int K)
{
    extern __shared__ char smem[];
    uint32_t sb = smem_u32(smem);

    int tid  = threadIdx.x;
    int warp = tid >> 5, lane = tid & 31;
    int g = lane >> 2, t = lane & 3;
    int wm = (warp & 1) * 64;
    int wn = (warp >> 1) * 64;
    int bm = blockIdx.y * 128;
    int bn = blockIdx.x * 128;

    float acc[4][8][4];
    #pragma unroll
    for (int mi = 0; mi < 4; mi++)
        #pragma unroll
        for (int ni = 0; ni < 8; ni++)
            #pragma unroll
            for (int c = 0; c < 4; c++) acc[mi][ni][c] = 0.f;

    const int KT = K >> 5;          // 64 stages of k=32

    auto fill = [&](int kt) {
        int kk = kt * 32;
        int s = kt % 3;
        #pragma unroll
        for (int p = 0; p < 4; p++) {              // A: 512 x 16B chunks
            int idx = tid + p * 128;
            int r = idx >> 2, c = idx & 3;
            uint32_t d = sb + s * GA2_ST + r * 80 + c * 16;
            const __half* src = A + (size_t)(bm + r) * K + kk + c * 8;
            asm volatile("cp.async.cg.shared.global [%0], [%1], 16;" :: "r"(d), "l"(src) : "memory");
        }
        #pragma unroll
        for (int p = 0; p < 4; p++) {              // B: 512 x 16B chunks
            int idx = tid + p * 128;
            int r = idx >> 2, c = idx & 3;
            uint32_t d = sb + GB2_BASE + s * GB2_ST + r * 80 + c * 16;
            const __half* src = W + (size_t)(bn + r) * K + kk + c * 8;
            asm volatile("cp.async.cg.shared.global [%0], [%1], 16;" :: "r"(d), "l"(src) : "memory");
        }
        asm volatile("cp.async.commit_group;" ::: "memory");
    };

    fill(0);
    fill(1);

    // ldmatrix lane-address components (constant across stages)
    uint32_t a_lane = (uint32_t)((lane & 15) * 80 + (lane >> 4) * 16);
    uint32_t b_lane = (uint32_t)(((lane & 7) + ((lane >> 4) << 3)) * 80 + ((lane >> 3) & 1) * 16);

    for (int kt = 0; kt < KT; kt++) {
        asm volatile("cp.async.wait_group 1;" ::: "memory");
        __syncthreads();                           // stage kt ready
        if (kt + 2 < KT) fill(kt + 2);

        int s = kt % 3;
        uint32_t Ab = sb + s * GA2_ST;
        uint32_t Bb = sb + GB2_BASE + s * GB2_ST;

        #pragma unroll
        for (int ks = 0; ks < 2; ks++) {           // two k16 steps per stage
            uint32_t af[4][4], bf[8][2];
            uint32_t abase = Ab + a_lane + ks * 32 + (uint32_t)(wm * 80);
            #pragma unroll
            for (int mi = 0; mi < 4; mi++) {
                uint32_t addr = abase + mi * (16 * 80);
                asm volatile(
                    "ldmatrix.sync.aligned.m8n8.x4.shared.b16 {%0,%1,%2,%3}, [%4];"
                    : "=r"(af[mi][0]), "=r"(af[mi][1]), "=r"(af[mi][2]), "=r"(af[mi][3])
                    : "r"(addr));
            }
            uint32_t bbase = Bb + b_lane + ks * 32 + (uint32_t)(wn * 80);
            #pragma unroll
            for (int np = 0; np < 4; np++) {
                uint32_t addr = bbase + np * (16 * 80);
                asm volatile(
                    "ldmatrix.sync.aligned.m8n8.x4.shared.b16 {%0,%1,%2,%3}, [%4];"
                    : "=r"(bf[2*np][0]), "=r"(bf[2*np][1]),
                      "=r"(bf[2*np+1][0]), "=r"(bf[2*np+1][1])
                    : "r"(addr));
            }
            #pragma unroll
            for (int mi = 0; mi < 4; mi++)
                #pragma unroll
                for (int ni = 0; ni < 8; ni++)
                    asm volatile(
                        "mma.sync.aligned.m16n8k16.row.col.f32.f16.f16.f32 "
                        "{%0,%1,%2,%3},{%4,%5,%6,%7},{%8,%9},{%0,%1,%2,%3};"
                        : "+f"(acc[mi][ni][0]), "+f"(acc[mi][ni][1]),
                          "+f"(acc[mi][ni][2]), "+f"(acc[mi][ni][3])
                        : "r"(af[mi][0]), "r"(af[mi][1]), "r"(af[mi][2]), "r"(af[mi][3]),
                          "r"(bf[ni][0]), "r"(bf[ni][1]));
        }
    }

    // ---- epilogue
    #pragma unroll
    for (int mi = 0; mi < 4; mi++) {
        int r0 = bm + wm + mi * 16 + g;
        #pragma unroll
        for (int ni = 0; ni < 8; ni++) {
            int c0 = bn + wn + ni * 8 + 2 * t;
            #pragma unroll
            for (int half_ = 0; half_ < 2; half_++) {
                int row = r0 + half_ * 8;
                float vx = acc[mi][ni][half_ * 2 + 0] + bias[c0];
                float vy = acc[mi][ni][half_ * 2 + 1] + bias[c0 + 1];
                if (RES) {
                    float2 rr = *(const float2*)(res + (size_t)row * N + c0);
                    vx += rr.x; vy += rr.y;
                }
                if (HOUT) {
                    *(__half2*)((__half*)Cv + (size_t)row * N + c0) =
                        __floats2half2_rn(vx, vy);
                } else {
                    float2 v; v.x = vx; v.y = vy;
                    *(float2*)((float*)Cv + (size_t)row * N + c0) = v;
                }
            }
        }
    }
}

// ---------------- fp16 tensor-core flash attention --------------------------
#define BLKQ 128
#define BLKK 64
#define FH 136                              /* smem row stride in halfs */
#define QB_H  (BLKQ * FH)                   /* 17408 halfs = 34816 B */
#define KVB_H (BLKK * FH)                   /* 8704 halfs = 17408 B */
#define FLASH_SMEM ((QB_H + 4 * KVB_H) * 2) /* 104448 B */

__global__ void __launch_bounds__(256) flash_f16_kernel(
    const __half* __restrict__ qkv, __half* __restrict__ o)
{
    extern __shared__ __half smh[];
    __half* Qs = smh;                        // [128][FH]
    __half* KV = smh + QB_H;                 // 2 x (K[64][FH], V[64][FH])

    int tid  = threadIdx.x;
    int warp = tid >> 5, lane = tid & 31;
    int g = lane >> 2, t = lane & 3;
    int qt = 15 - (int)blockIdx.x;           // heavy tiles first
    int bh = blockIdx.y;
    int b = bh >> 4, h = bh & 15;
    int q0 = qt * BLKQ;
    size_t rowbase = (size_t)b * SS;
    size_t hoff = (size_t)h * 128;
    const float scale = 0.08838834764831845f;   // 1/sqrt(128)

    // ---- load Q tile (fp16, 2048 x 16B chunks)
    #pragma unroll
    for (int i = 0; i < 8; i++) {
        int idx = tid + i * 256;
        int r = idx >> 4, c8 = (idx & 15) * 8;
        uint32_t d = smem_u32(Qs + r * FH + c8);
        const __half* src = qkv + (rowbase + q0 + r) * QKVN + hoff + c8;
        asm volatile("cp.async.cg.shared.global [%0], [%1], 16;" :: "r"(d), "l"(src) : "memory");
    }
    asm volatile("cp.async.commit_group;" ::: "memory");

    auto issue_tile = [&](int kt) {
        int kb = kt * BLKK;
        __half* Kb = KV + (kt & 1) * 2 * KVB_H;
        __half* Vb = Kb + KVB_H;
        #pragma unroll
        for (int i = 0; i < 4; i++) {
            int idx = tid + i * 256;         // 1024 x 16B chunks per operand
            int r = idx >> 4, c8 = (idx & 15) * 8;
            const __half* gk = qkv + (rowbase + kb + r) * QKVN + hoff + 2048 + c8;
            const __half* gv = gk + 2048;
            uint32_t sk = smem_u32(Kb + r * FH + c8);
            uint32_t sv = smem_u32(Vb + r * FH + c8);
            asm volatile("cp.async.cg.shared.global [%0], [%1], 16;" :: "r"(sk), "l"(gk) : "memory");
            asm volatile("cp.async.cg.shared.global [%0], [%1], 16;" :: "r"(sv), "l"(gv) : "memory");
        }
        asm volatile("cp.async.commit_group;" ::: "memory");
    };

    float m0 = -1e30f, m1 = -1e30f, l0 = 0.f, l1 = 0.f;
    float oa[16][4];
    #pragma unroll
    for (int nt = 0; nt < 16; nt++)
        #pragma unroll
        for (int c = 0; c < 4; c++) oa[nt][c] = 0.f;

    const int NKT = (q0 + BLKQ) / BLKK;      // 2*qt + 2
    const int myrow0 = q0 + warp * 16;
    // ldmatrix lane addresses (stride 272B rows -> conflict-free phases)
    uint32_t q_lm = smem_u32(Qs) +
        (uint32_t)((warp * 16 + (lane & 15)) * FH) * 2 + (uint32_t)((lane >> 4) * 16);
    uint32_t k_lane = (uint32_t)(((lane & 7) + ((lane >> 4) << 3)) * FH) * 2 +
                      (uint32_t)(((lane >> 3) & 1) * 16);
    uint32_t lm_base_off = (uint32_t)((lane & 15) * FH) * 2;

    issue_tile(0);

    for (int kt = 0; kt < NKT; kt++) {
        int kb = kt * BLKK;
        asm volatile("cp.async.wait_group 0;" ::: "memory");
        __syncthreads();
        if (kt + 1 < NKT) issue_tile(kt + 1);

        bool active = (kb <= myrow0 + 15);   // warp-uniform
        __half* Kb = KV + (kt & 1) * 2 * KVB_H;
        __half* Vb = Kb + KVB_H;

        if (active) {
            uint32_t kbase = smem_u32(Kb) + k_lane;
            uint32_t vbase = smem_u32(Vb) + lm_base_off;

            // ---- S = Q @ K^T   (64 k16 mmas/warp, ldmatrix-fed)
            float s[8][4];
            #pragma unroll
            for (int n = 0; n < 8; n++)
                #pragma unroll
                for (int c = 0; c < 4; c++) s[n][c] = 0.f;

            #pragma unroll
            for (int j = 0; j < 8; j++) {            // d chunks of 16
                uint32_t a0, a1, a2, a3;
                asm volatile(
                    "ldmatrix.sync.aligned.m8n8.x4.shared.b16 {%0,%1,%2,%3}, [%4];"
                    : "=r"(a0), "=r"(a1), "=r"(a2), "=r"(a3)
                    : "r"(q_lm + j * 32));
                uint32_t bf[8][2];
                #pragma unroll
                for (int np = 0; np < 4; np++) {
                    uint32_t addr = kbase + np * (16 * FH * 2) + j * 32;
                    asm volatile(
                        "ldmatrix.sync.aligned.m8n8.x4.shared.b16 {%0,%1,%2,%3}, [%4];"
                        : "=r"(bf[2*np][0]), "=r"(bf[2*np][1]),
                          "=r"(bf[2*np+1][0]), "=r"(bf[2*np+1][1])
                        : "r"(addr));
                }
                #pragma unroll
                for (int n = 0; n < 8; n++)
                    asm volatile(
                        "mma.sync.aligned.m16n8k16.row.col.f32.f16.f16.f32 "
                        "{%0,%1,%2,%3},{%4,%5,%6,%7},{%8,%9},{%0,%1,%2,%3};"
                        : "+f"(s[n][0]), "+f"(s[n][1]), "+f"(s[n][2]), "+f"(s[n][3])
                        : "r"(a0), "r"(a1), "r"(a2), "r"(a3),
                          "r"(bf[n][0]), "r"(bf[n][1]));
            }

            // ---- scale, then causal mask
            #pragma unroll
            for (int n = 0; n < 8; n++) {
                s[n][0] *= scale; s[n][1] *= scale;
                s[n][2] *= scale; s[n][3] *= scale;
            }
            if (kb + BLKK - 1 > myrow0) {
                int r0 = myrow0 + g, r1 = r0 + 8;
                #pragma unroll
                for (int n = 0; n < 8; n++) {
                    int c = kb + n * 8 + 2 * t;
                    if (c     > r0) s[n][0] = -1e30f;
                    if (c + 1 > r0) s[n][1] = -1e30f;
                    if (c     > r1) s[n][2] = -1e30f;
                    if (c + 1 > r1) s[n][3] = -1e30f;
                }
            }

            // ---- online softmax (rows g and g+8)
            float mx0 = -1e30f, mx1 = -1e30f;
            #pragma unroll
            for (int n = 0; n < 8; n++) {
                mx0 = fmaxf(mx0, fmaxf(s[n][0], s[n][1]));
                mx1 = fmaxf(mx1, fmaxf(s[n][2], s[n][3]));
            }
            mx0 = fmaxf(mx0, __shfl_xor_sync(0xffffffffu, mx0, 1));
            mx0 = fmaxf(mx0, __shfl_xor_sync(0xffffffffu, mx0, 2));
            mx1 = fmaxf(mx1, __shfl_xor_sync(0xffffffffu, mx1, 1));
            mx1 = fmaxf(mx1, __shfl_xor_sync(0xffffffffu, mx1, 2));
            float mn0 = fmaxf(m0, mx0), mn1 = fmaxf(m1, mx1);
            float al0 = __expf(m0 - mn0), al1 = __expf(m1 - mn1);
            float ls0 = 0.f, ls1 = 0.f;
            #pragma unroll
            for (int n = 0; n < 8; n++) {
                s[n][0] = __expf(s[n][0] - mn0);
                s[n][1] = __expf(s[n][1] - mn0);
                s[n][2] = __expf(s[n][2] - mn1);
                s[n][3] = __expf(s[n][3] - mn1);
                ls0 += s[n][0] + s[n][1];
                ls1 += s[n][2] + s[n][3];
            }
            ls0 += __shfl_xor_sync(0xffffffffu, ls0, 1);
            ls0 += __shfl_xor_sync(0xffffffffu, ls0, 2);
            ls1 += __shfl_xor_sync(0xffffffffu, ls1, 1);
            ls1 += __shfl_xor_sync(0xffffffffu, ls1, 2);
            l0 = l0 * al0 + ls0;  l1 = l1 * al1 + ls1;
            m0 = mn0;  m1 = mn1;
            #pragma unroll
            for (int nt = 0; nt < 16; nt++) {
                oa[nt][0] *= al0; oa[nt][1] *= al0;
                oa[nt][2] *= al1; oa[nt][3] *= al1;
            }

            // ---- O += P @ V   (P pack in regs; V via ldmatrix.x2.trans)
            #pragma unroll
            for (int j = 0; j < 4; j++) {            // seq chunks of 16
                __half2 pa0 = __floats2half2_rn(s[2*j    ][0], s[2*j    ][1]);
                __half2 pa1 = __floats2half2_rn(s[2*j    ][2], s[2*j    ][3]);
                __half2 pa2 = __floats2half2_rn(s[2*j + 1][0], s[2*j + 1][1]);
                __half2 pa3 = __floats2half2_rn(s[2*j + 1][2], s[2*j + 1][3]);
                uint32_t a0 = *(uint32_t*)&pa0;
                uint32_t a1 = *(uint32_t*)&pa1;
                uint32_t a2 = *(uint32_t*)&pa2;
                uint32_t a3 = *(uint32_t*)&pa3;
                uint32_t vrow = vbase + (uint32_t)(16 * j * FH) * 2;
                #pragma unroll
                for (int nt = 0; nt < 16; nt++) {
                    uint32_t b0, b1;
                    uint32_t addr = vrow + (uint32_t)(nt * 8) * 2;
                    asm volatile(
                        "ldmatrix.sync.aligned.m8n8.x2.trans.shared.b16 {%0, %1}, [%2];"
                        : "=r"(b0), "=r"(b1) : "r"(addr));
                    asm volatile(
                        "mma.sync.aligned.m16n8k16.row.col.f32.f16.f16.f32 "
                        "{%0,%1,%2,%3},{%4,%5,%6,%7},{%8,%9},{%0,%1,%2,%3};"
                        : "+f"(oa[nt][0]), "+f"(oa[nt][1]), "+f"(oa[nt][2]), "+f"(oa[nt][3])
                        : "r"(a0), "r"(a1), "r"(a2), "r"(a3), "r"(b0), "r"(b1));
                }
            }
        }
    }

    // ---- epilogue: normalize and store fp16 O
    float inv0 = 1.0f / l0, inv1 = 1.0f / l1;
    int r0 = q0 + warp * 16 + g;
    size_t ob0 = (rowbase + r0) * HH + hoff;
    size_t ob1 = ob0 + (size_t)8 * HH;
    #pragma unroll
    for (int nt = 0; nt < 16; nt++) {
        int col = nt * 8 + 2 * t;
        *(__half2*)(o + ob0 + col) = __floats2half2_rn(oa[nt][0] * inv0, oa[nt][1] * inv0);
        *(__half2*)(o + ob1 + col) = __floats2half2_rn(oa[nt][2] * inv1, oa[nt][3] * inv1);
    }
}

// ---------------- launch ----------------------------------------------------
extern "C" void kernel_launch(void* const* d_in, const int* in_sizes, int n_in,
                              void* d_out, int out_size)
{
    const float* x        = (const float*)d_in[0];
    const float* ln_w     = (const float*)d_in[1];
    const float* ln_b     = (const float*)d_in[2];
    const float* c_attn_w = (const float*)d_in[3];
    const float* c_attn_b = (const float*)d_in[4];
    const float* c_proj_w = (const float*)d_in[5];
    const float* c_proj_b = (const float*)d_in[6];
    float* out = (float*)d_out;

    void *p_xn, *p_qkv, *p_o, *p_wa, *p_wp;
    cudaGetSymbolAddress(&p_xn,  g_xn);
    cudaGetSymbolAddress(&p_qkv, g_qkv);
    cudaGetSymbolAddress(&p_o,   g_o);
    cudaGetSymbolAddress(&p_wa,  g_wa);
    cudaGetSymbolAddress(&p_wp,  g_wp);
    __half* xn  = (__half*)p_xn;
    __half* qkv = (__half*)p_qkv;
    __half* ov  = (__half*)p_o;
    __half* wa  = (__half*)p_wa;
    __half* wp  = (__half*)p_wp;

    cudaFuncSetAttribute((const void*)gemm_f16<false, true>,
                         cudaFuncAttributeMaxDynamicSharedMemorySize, GEMM_SMEM);
    cudaFuncSetAttribute((const void*)gemm_f16<true, false>,
                         cudaFuncAttributeMaxDynamicSharedMemorySize, GEMM_SMEM);
    cudaFuncSetAttribute((const void*)flash_f16_kernel,
                         cudaFuncAttributeMaxDynamicSharedMemorySize, FLASH_SMEM);

    // 0. transpose + fp16-cast weights to [N][K]
    transpose_h_kernel<<<dim3(QKVN / 32, HH / 32), 256>>>(c_attn_w, wa, HH, QKVN);
    transpose_h_kernel<<<dim3(HH / 32, HH / 32), 256>>>(c_proj_w, wp, HH, HH);

    // 1. LayerNorm (fp16 out)
    ln_kernel<<<MROWS, 256>>>(x, ln_w, ln_b, xn);

    // 2. QKV projection: [8192,2048] @ [2048,6144] + bias  -> fp16 qkv
    gemm_f16<false, true><<<dim3(QKVN / 128, MROWS / 128), 128, GEMM_SMEM>>>(
        xn, wa, c_attn_b, nullptr, qkv, MROWS, QKVN, HH);

    // 3. causal flash attention (fp16 tensor cores) -> fp16 O
    flash_f16_kernel<<<dim3(SS / BLKQ, BB * NHH), 256, FLASH_SMEM>>>(qkv, ov);

    // 4. output projection + bias + residual -> fp32 out
    gemm_f16<true, false><<<dim3(HH / 128, MROWS / 128), 128, GEMM_SMEM>>>(
        ov, wp, c_proj_b, x, out, MROWS, HH, HH);
}

// round 16
// speedup vs baseline: 3.8019x; 1.0423x over previous
#include <cuda_runtime.h>
#include <cuda_fp16.h>
#include <cstdint>

#define BB 4
#define SS 2048
#define HH 2048
#define NHH 16
#define HDD 128
#define MROWS (BB*SS)      /* 8192 */
#define QKVN (3*HH)        /* 6144 */

// ---------------- scratch (static device allocations are allowed) ----------
__device__ __half g_xn [(size_t)MROWS * HH];
__device__ __half g_qkv[(size_t)MROWS * QKVN];
__device__ __half g_o  [(size_t)MROWS * HH];
__device__ __half g_wa [(size_t)HH * QKVN];   // c_attn_w fp16, K-major [2048][6144]
__device__ __half g_wp [(size_t)HH * HH];     // c_proj_w fp16, K-major [2048][2048]

__device__ __forceinline__ uint32_t smem_u32(const void* p) {
    uint32_t a;
    asm("{ .reg .u64 t; cvta.to.shared.u64 t, %1; cvt.u32.u64 %0, t; }"
        : "=r"(a) : "l"(p));
    return a;
}

// ---------------- LayerNorm (float4 loads, writes fp16) ---------------------
__global__ void __launch_bounds__(256) ln_kernel(
    const float* __restrict__ x, const float* __restrict__ w,
    const float* __restrict__ b, __half* __restrict__ out)
{
    int row = blockIdx.x;
    const float4* xr = (const float4*)(x + (size_t)row * HH);
    float4 v[2];
    float s = 0.f, s2 = 0.f;
    #pragma unroll
    for (int i = 0; i < 2; i++) {
        v[i] = xr[threadIdx.x + i * 256];
        s  += v[i].x + v[i].y + v[i].z + v[i].w;
        s2 += v[i].x*v[i].x + v[i].y*v[i].y + v[i].z*v[i].z + v[i].w*v[i].w;
    }
    __shared__ float red0[8], red1[8];
    #pragma unroll
    for (int off = 16; off; off >>= 1) {
        s  += __shfl_xor_sync(0xffffffffu, s,  off);
        s2 += __shfl_xor_sync(0xffffffffu, s2, off);
    }
    int warp = threadIdx.x >> 5, lane = threadIdx.x & 31;
    if (lane == 0) { red0[warp] = s; red1[warp] = s2; }
    __syncthreads();
    if (warp == 0) {
        s  = red0[lane & 7];
        s2 = red1[lane & 7];
        #pragma unroll
        for (int off = 4; off; off >>= 1) {
            s  += __shfl_xor_sync(0xffffffffu, s,  off);
            s2 += __shfl_xor_sync(0xffffffffu, s2, off);
        }
        if (lane == 0) { red0[0] = s; red1[0] = s2; }
    }
    __syncthreads();
    float mu  = red0[0] * (1.f / HH);
    float var = red1[0] * (1.f / HH) - mu * mu;
    float rs  = rsqrtf(var + 1e-5f);
    size_t base = (size_t)row * HH;
    #pragma unroll
    for (int i = 0; i < 2; i++) {
        int c = (threadIdx.x + i * 256) * 4;
        float4 wv = *(const float4*)(w + c);
        float4 bv = *(const float4*)(b + c);
        __half2 h0 = __floats2half2_rn((v[i].x - mu) * rs * wv.x + bv.x,
                                       (v[i].y - mu) * rs * wv.y + bv.y);
        __half2 h1 = __floats2half2_rn((v[i].z - mu) * rs * wv.z + bv.z,
                                       (v[i].w - mu) * rs * wv.w + bv.w);
        *(__half2*)(out + base + c)     = h0;
        *(__half2*)(out + base + c + 2) = h1;
    }
}

// ---------------- streaming fp32 -> fp16 cast (coalesced) --------------------
__global__ void __launch_bounds__(256) cast_h_kernel(
    const float* __restrict__ in, __half* __restrict__ out)
{
    size_t i = ((size_t)blockIdx.x * 256 + threadIdx.x) * 4;
    float4 v = *(const float4*)(in + i);
    *(__half2*)(out + i)     = __floats2half2_rn(v.x, v.y);
    *(__half2*)(out + i + 2) = __floats2half2_rn(v.z, v.w);
}

// ---------------- fp16 GEMM: C[M,N] = A[M,K] @ W[K,N] + bias [+res] ---------
// Block tile 128(M) x 128(N), 128 threads (4 warps of 64x64), k-stage 32,
// 3-stage cp.async, 2 CTAs/SM. A frags via ldmatrix.x4 (80B stride);
// B read DIRECTLY from K-major W via ldmatrix.x4.trans (272B stride,
// conflict-free: r*17 mod 8 covers all banks) -- no weight transpose needed.
#define GA2_ST 10240                      /* 128 rows * 80B (40 halfs) */
#define GB2_ST 8704                       /* 32 k-rows * 272B (136 halfs) */
#define GB2_BASE (3 * GA2_ST)             /* 30720 */
#define GEMM_SMEM (GB2_BASE + 3 * GB2_ST) /* 56832 */
#define BSTRB 272                         /* B smem row stride in bytes */

template<bool RES, bool HOUT>
__global__ void __launch_bounds__(128, 2) gemm_f16(
    const __half* __restrict__ A, const __half* __restrict__ W,
    const float* __restrict__ bias, const float* __restrict__ res,
    void* __restrict__ Cv, int M, int N, int K)
{
    extern __shared__ char smem[];
    uint32_t sb = smem_u32(smem);

    int tid  = threadIdx.x;
    int warp = tid >> 5, lane = tid & 31;
    int g = lane >> 2, t = lane & 3;
    int wm = (warp & 1) * 64;
    int wn = (warp >> 1) * 64;
    int bm = blockIdx.y * 128;
    int bn = blockIdx.x * 128;

    float acc[4][8][4];
    #pragma unroll
    for (int mi = 0; mi < 4; mi++)
        #pragma unroll
        for (int ni = 0; ni < 8; ni++)
            #pragma unroll
            for (int c = 0; c < 4; c++) acc[mi][ni][c] = 0.f;

    const int KT = K >> 5;          // 64 stages of k=32

    auto fill = [&](int kt) {
        int kk = kt * 32;
        int s = kt % 3;
        #pragma unroll
        for (int p = 0; p < 4; p++) {              // A: 512 x 16B chunks
            int idx = tid + p * 128;
            int r = idx >> 2, c = idx & 3;
            uint32_t d = sb + s * GA2_ST + r * 80 + c * 16;
            const __half* src = A + (size_t)(bm + r) * K + kk + c * 8;
            asm volatile("cp.async.cg.shared.global [%0], [%1], 16;" :: "r"(d), "l"(src) : "memory");
        }
        #pragma unroll
        for (int p = 0; p < 4; p++) {              // B: 32 k-rows x 16 chunks
            int idx = tid + p * 128;
            int r = idx >> 4, c = idx & 15;        // r = k row, c = 16B chunk
            uint32_t d = sb + GB2_BASE + s * GB2_ST + r * BSTRB + c * 16;
            const __half* src = W + (size_t)(kk + r) * N + bn + c * 8;
            asm volatile("cp.async.cg.shared.global [%0], [%1], 16;" :: "r"(d), "l"(src) : "memory");
        }
        asm volatile("cp.async.commit_group;" ::: "memory");
    };

    fill(0);
    fill(1);

    // ldmatrix lane-address components (constant across stages)
    uint32_t a_lane = (uint32_t)((lane & 15) * 80 + (lane >> 4) * 16);
    // B x4.trans: group g2=lane>>3: matrices (k0-7,n), (k8-15,n), (k0-7,n+8), (k8-15,n+8)
    uint32_t b_lane = (uint32_t)(((lane & 7) + ((lane >> 3) & 1) * 8) * BSTRB +
                                 (lane >> 4) * 16);

    for (int kt = 0; kt < KT; kt++) {
        asm volatile("cp.async.wait_group 1;" ::: "memory");
        __syncthreads();                           // stage kt ready
        if (kt + 2 < KT) fill(kt + 2);

        int s = kt % 3;
        uint32_t Ab = sb + s * GA2_ST;
        uint32_t Bb = sb + GB2_BASE + s * GB2_ST + b_lane;

        #pragma unroll
        for (int ks = 0; ks < 2; ks++) {           // two k16 steps per stage
            uint32_t af[4][4], bf[8][2];
            uint32_t abase = Ab + a_lane + ks * 32 + (uint32_t)(wm * 80);
            #pragma unroll
            for (int mi = 0; mi < 4; mi++) {
                uint32_t addr = abase + mi * (16 * 80);
                asm volatile(
                    "ldmatrix.sync.aligned.m8n8.x4.shared.b16 {%0,%1,%2,%3}, [%4];"
                    : "=r"(af[mi][0]), "=r"(af[mi][1]), "=r"(af[mi][2]), "=r"(af[mi][3])
                    : "r"(addr));
            }
            uint32_t bbase = Bb + ks * (16 * BSTRB) + (uint32_t)(wn * 2);
            #pragma unroll
            for (int nb = 0; nb < 4; nb++) {       // 4 n16 blocks
                uint32_t addr = bbase + nb * 32;   // +16 cols = 32 bytes
                asm volatile(
                    "ldmatrix.sync.aligned.m8n8.x4.trans.shared.b16 {%0,%1,%2,%3}, [%4];"
                    : "=r"(bf[2*nb][0]), "=r"(bf[2*nb][1]),
                      "=r"(bf[2*nb+1][0]), "=r"(bf[2*nb+1][1])
                    : "r"(addr));
            }
            #pragma unroll
            for (int mi = 0; mi < 4; mi++)
                #pragma unroll
                for (int ni = 0; ni < 8; ni++)
                    asm volatile(
                        "mma.sync.aligned.m16n8k16.row.col.f32.f16.f16.f32 "
                        "{%0,%1,%2,%3},{%4,%5,%6,%7},{%8,%9},{%0,%1,%2,%3};"
                        : "+f"(acc[mi][ni][0]), "+f"(acc[mi][ni][1]),
                          "+f"(acc[mi][ni][2]), "+f"(acc[mi][ni][3])
                        : "r"(af[mi][0]), "r"(af[mi][1]), "r"(af[mi][2]), "r"(af[mi][3]),
                          "r"(bf[ni][0]), "r"(bf[ni][1]));
        }
    }

    // ---- epilogue
    #pragma unroll
    for (int mi = 0; mi < 4; mi++) {
        int r0 = bm + wm + mi * 16 + g;
        #pragma unroll
        for (int ni = 0; ni < 8; ni++) {
            int c0 = bn + wn + ni * 8 + 2 * t;
            #pragma unroll
            for (int half_ = 0; half_ < 2; half_++) {
                int row = r0 + half_ * 8;
                float vx = acc[mi][ni][half_ * 2 + 0] + bias[c0];
                float vy = acc[mi][ni][half_ * 2 + 1] + bias[c0 + 1];
                if (RES) {
                    float2 rr = *(const float2*)(res + (size_t)row * N + c0);
                    vx += rr.x; vy += rr.y;
                }
                if (HOUT) {
                    *(__half2*)((__half*)Cv + (size_t)row * N + c0) =
                        __floats2half2_rn(vx, vy);
                } else {
                    float2 v; v.x = vx; v.y = vy;
                    *(float2*)((float*)Cv + (size_t)row * N + c0) = v;
                }
            }
        }
    }
}

// ---------------- fp16 tensor-core flash attention --------------------------
#define BLKQ 128
#define BLKK 64
#define FH 136                              /* smem row stride in halfs */
#define QB_H  (BLKQ * FH)                   /* 17408 halfs = 34816 B */
#define KVB_H (BLKK * FH)                   /* 8704 halfs = 17408 B */
#define FLASH_SMEM ((QB_H + 4 * KVB_H) * 2) /* 104448 B */

__global__ void __launch_bounds__(256) flash_f16_kernel(
    const __half* __restrict__ qkv, __half* __restrict__ o)
{
    extern __shared__ __half smh[];
    __half* Qs = smh;                        // [128][FH]
    __half* KV = smh + QB_H;                 // 2 x (K[64][FH], V[64][FH])

    int tid  = threadIdx.x;
    int warp = tid >> 5, lane = tid & 31;
    int g = lane >> 2, t = lane & 3;
    int qt = 15 - (int)blockIdx.x;           // heavy tiles first
    int bh = blockIdx.y;
    int b = bh >> 4, h = bh & 15;
    int q0 = qt * BLKQ;
    size_t rowbase = (size_t)b * SS;
    size_t hoff = (size_t)h * 128;
    const float scale = 0.08838834764831845f;   // 1/sqrt(128)

    // ---- load Q tile (fp16, 2048 x 16B chunks)
    #pragma unroll
    for (int i = 0; i < 8; i++) {
        int idx = tid + i * 256;
        int r = idx >> 4, c8 = (idx & 15) * 8;
        uint32_t d = smem_u32(Qs + r * FH + c8);
        const __half* src = qkv + (rowbase + q0 + r) * QKVN + hoff + c8;
        asm volatile("cp.async.cg.shared.global [%0], [%1], 16;" :: "r"(d), "l"(src) : "memory");
    }
    asm volatile("cp.async.commit_group;" ::: "memory");

    auto issue_tile = [&](int kt) {
        int kb = kt * BLKK;
        __half* Kb = KV + (kt & 1) * 2 * KVB_H;
        __half* Vb = Kb + KVB_H;
        #pragma unroll
        for (int i = 0; i < 4; i++) {
            int idx = tid + i * 256;         // 1024 x 16B chunks per operand
            int r = idx >> 4, c8 = (idx & 15) * 8;
            const __half* gk = qkv + (rowbase + kb + r) * QKVN + hoff + 2048 + c8;
            const __half* gv = gk + 2048;
            uint32_t sk = smem_u32(Kb + r * FH + c8);
            uint32_t sv = smem_u32(Vb + r * FH + c8);
            asm volatile("cp.async.cg.shared.global [%0], [%1], 16;" :: "r"(sk), "l"(gk) : "memory");
            asm volatile("cp.async.cg.shared.global [%0], [%1], 16;" :: "r"(sv), "l"(gv) : "memory");
        }
        asm volatile("cp.async.commit_group;" ::: "memory");
    };

    float m0 = -1e30f, m1 = -1e30f, l0 = 0.f, l1 = 0.f;
    float oa[16][4];
    #pragma unroll
    for (int nt = 0; nt < 16; nt++)
        #pragma unroll
        for (int c = 0; c < 4; c++) oa[nt][c] = 0.f;

    const int NKT = (q0 + BLKQ) / BLKK;      // 2*qt + 2
    const int myrow0 = q0 + warp * 16;
    // ldmatrix lane addresses (stride 272B rows -> conflict-free phases)
    uint32_t q_lm = smem_u32(Qs) +
        (uint32_t)((warp * 16 + (lane & 15)) * FH) * 2 + (uint32_t)((lane >> 4) * 16);
    uint32_t k_lane = (uint32_t)(((lane & 7) + ((lane >> 4) << 3)) * FH) * 2 +
                      (uint32_t)(((lane >> 3) & 1) * 16);
    uint32_t lm_base_off = (uint32_t)((lane & 15) * FH) * 2;

    issue_tile(0);

    for (int kt = 0; kt < NKT; kt++) {
        int kb = kt * BLKK;
        asm volatile("cp.async.wait_group 0;" ::: "memory");
        __syncthreads();
        if (kt + 1 < NKT) issue_tile(kt + 1);

        bool active = (kb <= myrow0 + 15);   // warp-uniform
        __half* Kb = KV + (kt & 1) * 2 * KVB_H;
        __half* Vb = Kb + KVB_H;

        if (active) {
            uint32_t kbase = smem_u32(Kb) + k_lane;
            uint32_t vbase = smem_u32(Vb) + lm_base_off;

            // ---- S = Q @ K^T   (64 k16 mmas/warp, ldmatrix-fed)
            float s[8][4];
            #pragma unroll
            for (int n = 0; n < 8; n++)
                #pragma unroll
                for (int c = 0; c < 4; c++) s[n][c] = 0.f;

            #pragma unroll
            for (int j = 0; j < 8; j++) {            // d chunks of 16
                uint32_t a0, a1, a2, a3;
                asm volatile(
                    "ldmatrix.sync.aligned.m8n8.x4.shared.b16 {%0,%1,%2,%3}, [%4];"
                    : "=r"(a0), "=r"(a1), "=r"(a2), "=r"(a3)
                    : "r"(q_lm + j * 32));
                uint32_t bf[8][2];
                #pragma unroll
                for (int np = 0; np < 4; np++) {
                    uint32_t addr = kbase + np * (16 * FH * 2) + j * 32;
                    asm volatile(
                        "ldmatrix.sync.aligned.m8n8.x4.shared.b16 {%0,%1,%2,%3}, [%4];"
                        : "=r"(bf[2*np][0]), "=r"(bf[2*np][1]),
                          "=r"(bf[2*np+1][0]), "=r"(bf[2*np+1][1])
                        : "r"(addr));
                }
                #pragma unroll
                for (int n = 0; n < 8; n++)
                    asm volatile(
                        "mma.sync.aligned.m16n8k16.row.col.f32.f16.f16.f32 "
                        "{%0,%1,%2,%3},{%4,%5,%6,%7},{%8,%9},{%0,%1,%2,%3};"
                        : "+f"(s[n][0]), "+f"(s[n][1]), "+f"(s[n][2]), "+f"(s[n][3])
                        : "r"(a0), "r"(a1), "r"(a2), "r"(a3),
                          "r"(bf[n][0]), "r"(bf[n][1]));
            }

            // ---- scale, then causal mask
            #pragma unroll
            for (int n = 0; n < 8; n++) {
                s[n][0] *= scale; s[n][1] *= scale;
                s[n][2] *= scale; s[n][3] *= scale;
            }
            if (kb + BLKK - 1 > myrow0) {
                int r0 = myrow0 + g, r1 = r0 + 8;
                #pragma unroll
                for (int n = 0; n < 8; n++) {
                    int c = kb + n * 8 + 2 * t;
                    if (c     > r0) s[n][0] = -1e30f;
                    if (c + 1 > r0) s[n][1] = -1e30f;
                    if (c     > r1) s[n][2] = -1e30f;
                    if (c + 1 > r1) s[n][3] = -1e30f;
                }
            }

            // ---- online softmax (rows g and g+8)
            float mx0 = -1e30f, mx1 = -1e30f;
            #pragma unroll
            for (int n = 0; n < 8; n++) {
                mx0 = fmaxf(mx0, fmaxf(s[n][0], s[n][1]));
                mx1 = fmaxf(mx1, fmaxf(s[n][2], s[n][3]));
            }
            mx0 = fmaxf(mx0, __shfl_xor_sync(0xffffffffu, mx0, 1));
            mx0 = fmaxf(mx0, __shfl_xor_sync(0xffffffffu, mx0, 2));
            mx1 = fmaxf(mx1, __shfl_xor_sync(0xffffffffu, mx1, 1));
            mx1 = fmaxf(mx1, __shfl_xor_sync(0xffffffffu, mx1, 2));
            float mn0 = fmaxf(m0, mx0), mn1 = fmaxf(m1, mx1);
            float al0 = __expf(m0 - mn0), al1 = __expf(m1 - mn1);
            float ls0 = 0.f, ls1 = 0.f;
            #pragma unroll
            for (int n = 0; n < 8; n++) {
                s[n][0] = __expf(s[n][0] - mn0);
                s[n][1] = __expf(s[n][1] - mn0);
                s[n][2] = __expf(s[n][2] - mn1);
                s[n][3] = __expf(s[n][3] - mn1);
                ls0 += s[n][0] + s[n][1];
                ls1 += s[n][2] + s[n][3];
            }
            ls0 += __shfl_xor_sync(0xffffffffu, ls0, 1);
            ls0 += __shfl_xor_sync(0xffffffffu, ls0, 2);
            ls1 += __shfl_xor_sync(0xffffffffu, ls1, 1);
            ls1 += __shfl_xor_sync(0xffffffffu, ls1, 2);
            l0 = l0 * al0 + ls0;  l1 = l1 * al1 + ls1;
            m0 = mn0;  m1 = mn1;
            #pragma unroll
            for (int nt = 0; nt < 16; nt++) {
                oa[nt][0] *= al0; oa[nt][1] *= al0;
                oa[nt][2] *= al1; oa[nt][3] *= al1;
            }

            // ---- O += P @ V   (P pack in regs; V via ldmatrix.x2.trans)
            #pragma unroll
            for (int j = 0; j < 4; j++) {            // seq chunks of 16
                __half2 pa0 = __floats2half2_rn(s[2*j    ][0], s[2*j    ][1]);
                __half2 pa1 = __floats2half2_rn(s[2*j    ][2], s[2*j    ][3]);
                __half2 pa2 = __floats2half2_rn(s[2*j + 1][0], s[2*j + 1][1]);
                __half2 pa3 = __floats2half2_rn(s[2*j + 1][2], s[2*j + 1][3]);
                uint32_t a0 = *(uint32_t*)&pa0;
                uint32_t a1 = *(uint32_t*)&pa1;
                uint32_t a2 = *(uint32_t*)&pa2;
                uint32_t a3 = *(uint32_t*)&pa3;
                uint32_t vrow = vbase + (uint32_t)(16 * j * FH) * 2;
                #pragma unroll
                for (int nt = 0; nt < 16; nt++) {
                    uint32_t b0, b1;
                    uint32_t addr = vrow + (uint32_t)(nt * 8) * 2;
                    asm volatile(
                        "ldmatrix.sync.aligned.m8n8.x2.trans.shared.b16 {%0, %1}, [%2];"
                        : "=r"(b0), "=r"(b1) : "r"(addr));
                    asm volatile(
                        "mma.sync.aligned.m16n8k16.row.col.f32.f16.f16.f32 "
                        "{%0,%1,%2,%3},{%4,%5,%6,%7},{%8,%9},{%0,%1,%2,%3};"
                        : "+f"(oa[nt][0]), "+f"(oa[nt][1]), "+f"(oa[nt][2]), "+f"(oa[nt][3])
                        : "r"(a0), "r"(a1), "r"(a2), "r"(a3), "r"(b0), "r"(b1));
                }
            }
        }
    }

    // ---- epilogue: normalize and store fp16 O
    float inv0 = 1.0f / l0, inv1 = 1.0f / l1;
    int r0 = q0 + warp * 16 + g;
    size_t ob0 = (rowbase + r0) * HH + hoff;
    size_t ob1 = ob0 + (size_t)8 * HH;
    #pragma unroll
    for (int nt = 0; nt < 16; nt++) {
        int col = nt * 8 + 2 * t;
        *(__half2*)(o + ob0 + col) = __floats2half2_rn(oa[nt][0] * inv0, oa[nt][1] * inv0);
        *(__half2*)(o + ob1 + col) = __floats2half2_rn(oa[nt][2] * inv1, oa[nt][3] * inv1);
    }
}

// ---------------- launch ----------------------------------------------------
extern "C" void kernel_launch(void* const* d_in, const int* in_sizes, int n_in,
                              void* d_out, int out_size)
{
    const float* x        = (const float*)d_in[0];
    const float* ln_w     = (const float*)d_in[1];
    const float* ln_b     = (const float*)d_in[2];
    const float* c_attn_w = (const float*)d_in[3];
    const float* c_attn_b = (const float*)d_in[4];
    const float* c_proj_w = (const float*)d_in[5];
    const float* c_proj_b = (const float*)d_in[6];
    float* out = (float*)d_out;

    void *p_xn, *p_qkv, *p_o, *p_wa, *p_wp;
    cudaGetSymbolAddress(&p_xn,  g_xn);
    cudaGetSymbolAddress(&p_qkv, g_qkv);
    cudaGetSymbolAddress(&p_o,   g_o);
    cudaGetSymbolAddress(&p_wa,  g_wa);
    cudaGetSymbolAddress(&p_wp,  g_wp);
    __half* xn  = (__half*)p_xn;
    __half* qkv = (__half*)p_qkv;
    __half* ov  = (__half*)p_o;
    __half* wa  = (__half*)p_wa;
    __half* wp  = (__half*)p_wp;

    cudaFuncSetAttribute((const void*)gemm_f16<false, true>,
                         cudaFuncAttributeMaxDynamicSharedMemorySize, GEMM_SMEM);
    cudaFuncSetAttribute((const void*)gemm_f16<true, false>,
                         cudaFuncAttributeMaxDynamicSharedMemorySize, GEMM_SMEM);
    cudaFuncSetAttribute((const void*)flash_f16_kernel,
                         cudaFuncAttributeMaxDynamicSharedMemorySize, FLASH_SMEM);

    // 0. cast weights to fp16 (keep K-major layout; no transpose needed)
    cast_h_kernel<<<(HH * QKVN) / 1024, 256>>>(c_attn_w, wa);
    cast_h_kernel<<<(HH * HH) / 1024, 256>>>(c_proj_w, wp);

    // 1. LayerNorm (fp16 out)
    ln_kernel<<<MROWS, 256>>>(x, ln_w, ln_b, xn);

    // 2. QKV projection: [8192,2048] @ [2048,6144] + bias  -> fp16 qkv
    gemm_f16<false, true><<<dim3(QKVN / 128, MROWS / 128), 128, GEMM_SMEM>>>(
        xn, wa, c_attn_b, nullptr, qkv, MROWS, QKVN, HH);

    // 3. causal flash attention (fp16 tensor cores) -> fp16 O
    flash_f16_kernel<<<dim3(SS / BLKQ, BB * NHH), 256, FLASH_SMEM>>>(qkv, ov);

    // 4. output projection + bias + residual -> fp32 out
    gemm_f16<true, false><<<dim3(HH / 128, MROWS / 128), 128, GEMM_SMEM>>>(
        ov, wp, c_proj_b, x, out, MROWS, HH, HH);
}